// round 1
// baseline (speedup 1.0000x reference)
#include <cuda_runtime.h>
#include <math.h>

#define NB 32
#define NS 2048
#define NQ 1024
#define NI 1024
#define NA 1024
#define NCH 16   // s-chunks for blended partial accumulation

// scratch (device globals: allocation-free per harness rules)
__device__ float g_pq[NB * NA];
__device__ float g_react[NB * NS];
__device__ float g_bpart[NB * NCH * NI];

// ---------------------------------------------------------------------------
// Kernel 1: pq[b,a] = sum_q queries[b,0,q] * W[q,a]
// ---------------------------------------------------------------------------
__global__ void pq_kernel(const float* __restrict__ queries,
                          const float* __restrict__ W)
{
    const int b = blockIdx.x;
    const int a = blockIdx.y * 256 + threadIdx.x;
    __shared__ float qs[NQ];
    for (int i = threadIdx.x; i < NQ; i += 256) qs[i] = queries[b * NQ + i];
    __syncthreads();
    float acc = 0.f;
#pragma unroll 8
    for (int q = 0; q < NQ; q++) acc = fmaf(qs[q], W[(size_t)q * NA + a], acc);
    g_pq[b * NA + a] = acc;
}

// ---------------------------------------------------------------------------
// Kernel 2 (dominant): fused GEMM + tanh + dot(v) reduction.
// react[m] = sum_n v[n] * tanh( pq[b(m),n] + sum_k items[m,k]*U[k,n] )
// Tile BMxBN=128x128, BK=16, 256 threads, 8x8 per thread.
// Each CTA sweeps all 8 n-tiles so its items slice stays L2-resident.
// ---------------------------------------------------------------------------
#define BM 128
#define BN 128
#define BK 16
#define TM 8
#define TN 8

__global__ __launch_bounds__(256, 2)
void react_kernel(const float* __restrict__ items,
                  const float* __restrict__ U,
                  const float* __restrict__ v)
{
    __shared__ float As[BK][BM];
    __shared__ float Bs[BK][BN];

    const int t  = threadIdx.x;
    const int tm = t >> 4;      // 0..15
    const int tn = t & 15;      // 0..15
    const int m0 = blockIdx.x * BM;
    const int b  = m0 / NS;     // BM divides S -> tile within one batch
    const float* __restrict__ pqb = g_pq + b * NA;

    // loader indices: 512 float4 loads per tile, 2 per thread
    const int i0 = 2 * t, i1 = 2 * t + 1;
    const int ar0 = i0 >> 2, ac0 = (i0 & 3) << 2;
    const int ar1 = i1 >> 2, ac1 = (i1 & 3) << 2;
    const int br0 = i0 >> 5, bc0 = (i0 & 31) << 2;
    const int br1 = i1 >> 5, bc1 = (i1 & 31) << 2;

    const float* itA0 = items + (size_t)(m0 + ar0) * NI;
    const float* itA1 = items + (size_t)(m0 + ar1) * NI;

    float partial[TM];
#pragma unroll
    for (int i = 0; i < TM; i++) partial[i] = 0.f;

    for (int nt = 0; nt < NA / BN; nt++) {
        const int n0 = nt * BN;
        float acc[TM][TN];
#pragma unroll
        for (int i = 0; i < TM; i++)
#pragma unroll
            for (int j = 0; j < TN; j++) acc[i][j] = 0.f;

        // prefetch k-tile 0
        float4 pa0 = *(const float4*)(itA0 + ac0);
        float4 pa1 = *(const float4*)(itA1 + ac1);
        float4 pb0 = *(const float4*)(U + (size_t)br0 * NA + n0 + bc0);
        float4 pb1 = *(const float4*)(U + (size_t)br1 * NA + n0 + bc1);

        for (int kt = 0; kt < NI / BK; kt++) {
            __syncthreads();   // previous compute done reading smem
            As[ac0 + 0][ar0] = pa0.x; As[ac0 + 1][ar0] = pa0.y;
            As[ac0 + 2][ar0] = pa0.z; As[ac0 + 3][ar0] = pa0.w;
            As[ac1 + 0][ar1] = pa1.x; As[ac1 + 1][ar1] = pa1.y;
            As[ac1 + 2][ar1] = pa1.z; As[ac1 + 3][ar1] = pa1.w;
            *(float4*)&Bs[br0][bc0] = pb0;
            *(float4*)&Bs[br1][bc1] = pb1;
            __syncthreads();

            if (kt + 1 < NI / BK) {   // register prefetch of next k-tile
                const int k1 = (kt + 1) * BK;
                pa0 = *(const float4*)(itA0 + k1 + ac0);
                pa1 = *(const float4*)(itA1 + k1 + ac1);
                pb0 = *(const float4*)(U + (size_t)(k1 + br0) * NA + n0 + bc0);
                pb1 = *(const float4*)(U + (size_t)(k1 + br1) * NA + n0 + bc1);
            }

#pragma unroll
            for (int kk = 0; kk < BK; kk++) {
                float af[TM], bf[TN];
#pragma unroll
                for (int i = 0; i < TM; i++) af[i] = As[kk][tm * TM + i];
#pragma unroll
                for (int j = 0; j < TN; j++) bf[j] = Bs[kk][tn * TN + j];
#pragma unroll
                for (int i = 0; i < TM; i++)
#pragma unroll
                    for (int j = 0; j < TN; j++)
                        acc[i][j] = fmaf(af[i], bf[j], acc[i][j]);
            }
        }

        // fused epilogue for this n-tile: tanh + dot with v, folded into partial
#pragma unroll
        for (int j = 0; j < TN; j++) {
            const int n   = n0 + tn * TN + j;
            const float pqn = __ldg(pqb + n);
            const float vn  = __ldg(v + n);
#pragma unroll
            for (int i = 0; i < TM; i++)
                partial[i] += tanhf(acc[i][j] + pqn) * vn;
        }
    }

    // reduce partials across the 16 tn-lanes (contiguous within half-warp)
#pragma unroll
    for (int i = 0; i < TM; i++) {
        float val = partial[i];
        val += __shfl_down_sync(0xffffffffu, val, 8, 16);
        val += __shfl_down_sync(0xffffffffu, val, 4, 16);
        val += __shfl_down_sync(0xffffffffu, val, 2, 16);
        val += __shfl_down_sync(0xffffffffu, val, 1, 16);
        if (tn == 0) g_react[m0 + tm * TM + i] = val;
    }
}

// ---------------------------------------------------------------------------
// Kernel 3: masked softmax over S per batch; writes scores into out.
// ---------------------------------------------------------------------------
__global__ void softmax_kernel(const int* __restrict__ weights,
                               float* __restrict__ out)
{
    const int b = blockIdx.x;
    const int t = threadIdx.x;
    __shared__ float sm[256];

    float vals[NS / 256];
    float mx = -INFINITY;
#pragma unroll
    for (int r = 0; r < NS / 256; r++) {
        const int s = t + r * 256;
        const float x = (weights[b * NS + s] == 0) ? -INFINITY
                                                   : g_react[b * NS + s];
        vals[r] = x;
        mx = fmaxf(mx, x);
    }
    sm[t] = mx; __syncthreads();
    for (int off = 128; off > 0; off >>= 1) {
        if (t < off) sm[t] = fmaxf(sm[t], sm[t + off]);
        __syncthreads();
    }
    mx = sm[0];
    __syncthreads();

    float sum = 0.f;
#pragma unroll
    for (int r = 0; r < NS / 256; r++) {
        vals[r] = expf(vals[r] - mx);   // exp(-inf - mx) == 0 handles mask
        sum += vals[r];
    }
    sm[t] = sum; __syncthreads();
    for (int off = 128; off > 0; off >>= 1) {
        if (t < off) sm[t] += sm[t + off];
        __syncthreads();
    }
    const float inv = 1.f / sm[0];

    float* scores = out + NB * NI + (size_t)b * NS;
#pragma unroll
    for (int r = 0; r < NS / 256; r++)
        scores[t + r * 256] = vals[r] * inv;
}

// ---------------------------------------------------------------------------
// Kernel 4a: blended partials per (b, s-chunk) — deterministic (no atomics)
// ---------------------------------------------------------------------------
__global__ void blend_partial_kernel(const float* __restrict__ items,
                                     const float* __restrict__ out)
{
    const int b  = blockIdx.x;
    const int ch = blockIdx.y;
    const int s0 = ch * (NS / NCH);
    const float* __restrict__ scores = out + NB * NI + (size_t)b * NS;
    const float* __restrict__ base   = items + (size_t)b * NS * NI;
    const int i = threadIdx.x * 4;

    float4 acc = make_float4(0.f, 0.f, 0.f, 0.f);
    for (int s = 0; s < NS / NCH; s++) {
        const float w = scores[s0 + s];
        if (w != 0.f) {   // masked rows have exactly-zero score: skip the read
            const float4 x = *(const float4*)(base + (size_t)(s0 + s) * NI + i);
            acc.x = fmaf(w, x.x, acc.x);
            acc.y = fmaf(w, x.y, acc.y);
            acc.z = fmaf(w, x.z, acc.z);
            acc.w = fmaf(w, x.w, acc.w);
        }
    }
    *(float4*)(g_bpart + (size_t)(b * NCH + ch) * NI + i) = acc;
}

// ---------------------------------------------------------------------------
// Kernel 4b: reduce partials -> blended (first NB*NI floats of out)
// ---------------------------------------------------------------------------
__global__ void blend_reduce_kernel(float* __restrict__ out)
{
    const int b = blockIdx.x;
    const int i = threadIdx.x * 4;
    float4 acc = make_float4(0.f, 0.f, 0.f, 0.f);
    for (int c = 0; c < NCH; c++) {
        const float4 x = *(const float4*)(g_bpart + (size_t)(b * NCH + c) * NI + i);
        acc.x += x.x; acc.y += x.y; acc.z += x.z; acc.w += x.w;
    }
    *(float4*)(out + (size_t)b * NI + i) = acc;
}

// ---------------------------------------------------------------------------
extern "C" void kernel_launch(void* const* d_in, const int* in_sizes, int n_in,
                              void* d_out, int out_size)
{
    const float* queries = (const float*)d_in[0];   // [B,1,Q]
    const float* items   = (const float*)d_in[1];   // [B,S,I]
    const int*   weights = (const int*)  d_in[2];   // [B,S]
    const float* W       = (const float*)d_in[3];   // [Q,A]
    const float* U       = (const float*)d_in[4];   // [I,A]
    const float* v       = (const float*)d_in[5];   // [A]
    float* out = (float*)d_out;   // [B*I blended | B*S scores]

    pq_kernel<<<dim3(NB, NA / 256), 256>>>(queries, W);
    react_kernel<<<(NB * NS) / BM, 256>>>(items, U, v);
    softmax_kernel<<<NB, 256>>>(weights, out);
    blend_partial_kernel<<<dim3(NB, NCH), 256>>>(items, out);
    blend_reduce_kernel<<<NB, 256>>>(out);
}

// round 2
// speedup vs baseline: 1.9606x; 1.9606x over previous
#include <cuda_runtime.h>
#include <math.h>

#define NB 32
#define NS 2048
#define NQ 1024
#define NI 1024
#define NA 1024
#define NCH 16

typedef unsigned long long ull;

// scratch (device globals: allocation-free per harness rules)
__device__ float g_pq[NB * NA];
__device__ float g_react[NB * NS];
__device__ float g_bpart[NB * NCH * NI];
__device__ int   g_sidx[NB * NS];
__device__ int   g_cnt[NB];

// packed dual-fp32 FMA (SASS FFMA2) — exact fp32 per lane
#define FMA2(d, a, b) asm("fma.rn.f32x2 %0, %1, %2, %0;" : "+l"(d) : "l"(a), "l"(b))

// ---------------------------------------------------------------------------
// Kernel 0: per-batch compaction of active s-indices (warp ballot scan)
// ---------------------------------------------------------------------------
__global__ void compact_kernel(const int* __restrict__ weights)
{
    const int b = blockIdx.x;
    const int lane = threadIdx.x;   // 32 threads
    int base = 0;
    for (int c = 0; c < NS / 32; c++) {
        const int s = c * 32 + lane;
        const int active = (weights[b * NS + s] != 0);
        const unsigned m = __ballot_sync(0xffffffffu, active);
        const int pre = __popc(m & ((1u << lane) - 1u));
        if (active) g_sidx[b * NS + base + pre] = s;
        base += __popc(m);
    }
    if (lane == 0) g_cnt[b] = base;
}

// ---------------------------------------------------------------------------
// Kernel 1: pq[b,a] = sum_q queries[b,0,q] * W[q,a]
// ---------------------------------------------------------------------------
__global__ void pq_kernel(const float* __restrict__ queries,
                          const float* __restrict__ W)
{
    const int b = blockIdx.x;
    const int a = blockIdx.y * 256 + threadIdx.x;
    __shared__ float qs[NQ];
    for (int i = threadIdx.x; i < NQ; i += 256) qs[i] = queries[b * NQ + i];
    __syncthreads();
    float acc = 0.f;
#pragma unroll 8
    for (int q = 0; q < NQ; q++) acc = fmaf(qs[q], W[(size_t)q * NA + a], acc);
    g_pq[b * NA + a] = acc;
}

// ---------------------------------------------------------------------------
// Kernel 2 (dominant): compacted fused GEMM + tanh + dot(v) via f32x2 FMA.
// Only active rows (weights!=0) are computed. Accumulators are f32x2 pairs
// along n; A smem is stored pre-duplicated so the broadcast operand loads as
// ready f32x2 dups (no packing in the inner loop).
// Per-thread tile: 8 m-rows x 8 n-cols as 4 chunks of 2 (conflict-free LDS.64).
// ---------------------------------------------------------------------------
#define BM 128
#define BN 128
#define BK 16

__global__ __launch_bounds__(256, 2)
void react_kernel(const float* __restrict__ items,
                  const float* __restrict__ U,
                  const float* __restrict__ v)
{
    __shared__ float As2[BK][2 * BM];  // duplicated: As2[k][2m] = As2[k][2m+1] = A[k][m]
    __shared__ float Bs[BK][BN];

    const int b    = blockIdx.y;
    const int tile = blockIdx.x;
    const int cnt  = g_cnt[b];
    const int m0   = tile * BM;
    if (m0 >= cnt) return;

    const int t  = threadIdx.x;
    const int tm = t >> 4;      // 0..15
    const int tn = t & 15;      // 0..15

    // loader indices: 512 float4 loads per k-tile, 2 per thread
    const int i0 = 2 * t, i1 = 2 * t + 1;
    const int ar0 = i0 >> 2, ac0 = (i0 & 3) << 2;
    const int ar1 = i1 >> 2, ac1 = (i1 & 3) << 2;
    const int br0 = i0 >> 5, bc0 = (i0 & 31) << 2;
    const int br1 = i1 >> 5, bc1 = (i1 & 31) << 2;

    // gathered A row pointers (clamped: tail duplicates are idempotent)
    const int cl  = cnt - 1;
    const int sr0 = g_sidx[b * NS + min(m0 + ar0, cl)];
    const int sr1 = g_sidx[b * NS + min(m0 + ar1, cl)];
    const float* __restrict__ itA0 = items + ((size_t)b * NS + sr0) * NI;
    const float* __restrict__ itA1 = items + ((size_t)b * NS + sr1) * NI;
    const float* __restrict__ pqb  = g_pq + b * NA;

    float partial[8];
#pragma unroll
    for (int i = 0; i < 8; i++) partial[i] = 0.f;

    for (int nt = 0; nt < NA / BN; nt++) {
        const int n0 = nt * BN;
        ull acc[8][4];
#pragma unroll
        for (int i = 0; i < 8; i++)
#pragma unroll
            for (int c = 0; c < 4; c++) acc[i][c] = 0ull;  // (+0.f, +0.f)

        // prefetch k-tile 0
        float4 pa0 = *(const float4*)(itA0 + ac0);
        float4 pa1 = *(const float4*)(itA1 + ac1);
        float4 pb0 = *(const float4*)(U + (size_t)br0 * NA + n0 + bc0);
        float4 pb1 = *(const float4*)(U + (size_t)br1 * NA + n0 + bc1);

        for (int kt = 0; kt < NI / BK; kt++) {
            __syncthreads();   // previous compute done reading smem
            // A: store duplicated pairs (STS.64 each)
            *(float2*)&As2[ac0 + 0][2 * ar0] = make_float2(pa0.x, pa0.x);
            *(float2*)&As2[ac0 + 1][2 * ar0] = make_float2(pa0.y, pa0.y);
            *(float2*)&As2[ac0 + 2][2 * ar0] = make_float2(pa0.z, pa0.z);
            *(float2*)&As2[ac0 + 3][2 * ar0] = make_float2(pa0.w, pa0.w);
            *(float2*)&As2[ac1 + 0][2 * ar1] = make_float2(pa1.x, pa1.x);
            *(float2*)&As2[ac1 + 1][2 * ar1] = make_float2(pa1.y, pa1.y);
            *(float2*)&As2[ac1 + 2][2 * ar1] = make_float2(pa1.z, pa1.z);
            *(float2*)&As2[ac1 + 3][2 * ar1] = make_float2(pa1.w, pa1.w);
            *(float4*)&Bs[br0][bc0] = pb0;
            *(float4*)&Bs[br1][bc1] = pb1;
            __syncthreads();

            if (kt + 1 < NI / BK) {   // register prefetch of next k-tile
                const int k1 = (kt + 1) * BK;
                pa0 = *(const float4*)(itA0 + k1 + ac0);
                pa1 = *(const float4*)(itA1 + k1 + ac1);
                pb0 = *(const float4*)(U + (size_t)(k1 + br0) * NA + n0 + bc0);
                pb1 = *(const float4*)(U + (size_t)(k1 + br1) * NA + n0 + bc1);
            }

#pragma unroll
            for (int kk = 0; kk < BK; kk++) {
                // 8 duplicated af values: 4x LDS.128 (16-lane broadcast groups)
                const ulonglong2* pa = (const ulonglong2*)&As2[kk][16 * tm];
                const ulonglong2 q0 = pa[0], q1 = pa[1], q2 = pa[2], q3 = pa[3];
                ull af[8];
                af[0] = q0.x; af[1] = q0.y; af[2] = q1.x; af[3] = q1.y;
                af[4] = q2.x; af[5] = q2.y; af[6] = q3.x; af[7] = q3.y;
                // 4 bf pairs: LDS.64, lane addresses 8B apart -> conflict-free
                ull bf[4];
#pragma unroll
                for (int c = 0; c < 4; c++)
                    bf[c] = *(const ull*)&Bs[kk][c * 32 + 2 * tn];
#pragma unroll
                for (int i = 0; i < 8; i++)
#pragma unroll
                    for (int c = 0; c < 4; c++)
                        FMA2(acc[i][c], af[i], bf[c]);
            }
        }

        // fused epilogue: tanh + dot with v, folded into per-row partials
#pragma unroll
        for (int c = 0; c < 4; c++) {
            const int n = n0 + c * 32 + 2 * tn;
            const float2 pq2 = *(const float2*)(pqb + n);
            const float2 v2  = *(const float2*)(v + n);
#pragma unroll
            for (int i = 0; i < 8; i++) {
                ull a = acc[i][c];
                float2 f = *reinterpret_cast<float2*>(&a);
                partial[i] += tanhf(f.x + pq2.x) * v2.x
                            + tanhf(f.y + pq2.y) * v2.y;
            }
        }
    }

    // reduce partials across the 16 tn-lanes, scatter to original s index
#pragma unroll
    for (int i = 0; i < 8; i++) {
        float val = partial[i];
        val += __shfl_down_sync(0xffffffffu, val, 8, 16);
        val += __shfl_down_sync(0xffffffffu, val, 4, 16);
        val += __shfl_down_sync(0xffffffffu, val, 2, 16);
        val += __shfl_down_sync(0xffffffffu, val, 1, 16);
        if (tn == 0) {
            const int ml = m0 + tm * 8 + i;
            const int s  = g_sidx[b * NS + min(ml, cl)];
            g_react[b * NS + s] = val;   // duplicates write identical values
        }
    }
}

// ---------------------------------------------------------------------------
// Kernel 3: masked softmax over S per batch; writes scores into out.
// ---------------------------------------------------------------------------
__global__ void softmax_kernel(const int* __restrict__ weights,
                               float* __restrict__ out)
{
    const int b = blockIdx.x;
    const int t = threadIdx.x;
    __shared__ float sm[256];

    float vals[NS / 256];
    float mx = -INFINITY;
#pragma unroll
    for (int r = 0; r < NS / 256; r++) {
        const int s = t + r * 256;
        const float x = (weights[b * NS + s] == 0) ? -INFINITY
                                                   : g_react[b * NS + s];
        vals[r] = x;
        mx = fmaxf(mx, x);
    }
    sm[t] = mx; __syncthreads();
    for (int off = 128; off > 0; off >>= 1) {
        if (t < off) sm[t] = fmaxf(sm[t], sm[t + off]);
        __syncthreads();
    }
    mx = sm[0];
    __syncthreads();

    float sum = 0.f;
#pragma unroll
    for (int r = 0; r < NS / 256; r++) {
        vals[r] = expf(vals[r] - mx);   // exp(-inf - mx) == 0 handles mask
        sum += vals[r];
    }
    sm[t] = sum; __syncthreads();
    for (int off = 128; off > 0; off >>= 1) {
        if (t < off) sm[t] += sm[t + off];
        __syncthreads();
    }
    const float inv = 1.f / sm[0];

    float* scores = out + NB * NI + (size_t)b * NS;
#pragma unroll
    for (int r = 0; r < NS / 256; r++)
        scores[t + r * 256] = vals[r] * inv;
}

// ---------------------------------------------------------------------------
// Kernel 4a: blended partials per (b, s-chunk) — deterministic (no atomics)
// ---------------------------------------------------------------------------
__global__ void blend_partial_kernel(const float* __restrict__ items,
                                     const float* __restrict__ out)
{
    const int b  = blockIdx.x;
    const int ch = blockIdx.y;
    const int s0 = ch * (NS / NCH);
    const float* __restrict__ scores = out + NB * NI + (size_t)b * NS;
    const float* __restrict__ base   = items + (size_t)b * NS * NI;
    const int i = threadIdx.x * 4;

    float4 acc = make_float4(0.f, 0.f, 0.f, 0.f);
    for (int s = 0; s < NS / NCH; s++) {
        const float w = scores[s0 + s];
        if (w != 0.f) {   // masked rows have exactly-zero score: skip the read
            const float4 x = *(const float4*)(base + (size_t)(s0 + s) * NI + i);
            acc.x = fmaf(w, x.x, acc.x);
            acc.y = fmaf(w, x.y, acc.y);
            acc.z = fmaf(w, x.z, acc.z);
            acc.w = fmaf(w, x.w, acc.w);
        }
    }
    *(float4*)(g_bpart + (size_t)(b * NCH + ch) * NI + i) = acc;
}

// ---------------------------------------------------------------------------
// Kernel 4b: reduce partials -> blended (first NB*NI floats of out)
// ---------------------------------------------------------------------------
__global__ void blend_reduce_kernel(float* __restrict__ out)
{
    const int b = blockIdx.x;
    const int i = threadIdx.x * 4;
    float4 acc = make_float4(0.f, 0.f, 0.f, 0.f);
    for (int c = 0; c < NCH; c++) {
        const float4 x = *(const float4*)(g_bpart + (size_t)(b * NCH + c) * NI + i);
        acc.x += x.x; acc.y += x.y; acc.z += x.z; acc.w += x.w;
    }
    *(float4*)(out + (size_t)b * NI + i) = acc;
}

// ---------------------------------------------------------------------------
extern "C" void kernel_launch(void* const* d_in, const int* in_sizes, int n_in,
                              void* d_out, int out_size)
{
    const float* queries = (const float*)d_in[0];   // [B,1,Q]
    const float* items   = (const float*)d_in[1];   // [B,S,I]
    const int*   weights = (const int*)  d_in[2];   // [B,S]
    const float* W       = (const float*)d_in[3];   // [Q,A]
    const float* U       = (const float*)d_in[4];   // [I,A]
    const float* v       = (const float*)d_in[5];   // [A]
    float* out = (float*)d_out;   // [B*I blended | B*S scores]

    compact_kernel<<<NB, 32>>>(weights);
    pq_kernel<<<dim3(NB, NA / 256), 256>>>(queries, W);
    react_kernel<<<dim3(NS / BM, NB), 256>>>(items, U, v);
    softmax_kernel<<<NB, 256>>>(weights, out);
    blend_partial_kernel<<<dim3(NB, NCH), 256>>>(items, out);
    blend_reduce_kernel<<<NB, 256>>>(out);
}

// round 4
// speedup vs baseline: 4.2896x; 2.1880x over previous
#include <cuda_runtime.h>
#include <cuda_bf16.h>
#include <math.h>
#include <stdint.h>

#define NB 32
#define NS 2048
#define NQ 1024
#define NI 1024
#define NA 1024
#define NCH 16

// ---- react tiling ----
#define BMT 128                 // CTA m tile
#define BNT 128                 // CTA n tile
#define BK  32                  // k per stage
#define PITCH 56                // bf16 elems per smem row (112B: conflict-free ldmatrix)
#define TILEB (128 * PITCH * 2) // 14336 bytes per operand tile
#define BUFSZ (4 * TILEB)       // AH, AL, BH, BL
#define OFF_AH 0
#define OFF_AL (1 * TILEB)
#define OFF_BH (2 * TILEB)
#define OFF_BL (3 * TILEB)
#define OFF_PQ (2 * BUFSZ)          // 114688
#define OFF_V  (OFF_PQ + 4096)
#define OFF_RED (OFF_V + 4096)
#define SM_TOTAL (OFF_RED + 1024)   // 123904 bytes

// scratch (device globals: allocation-free per harness rules)
__device__ float g_pq[NB * NA];
__device__ float g_react[NB * NS];
__device__ float g_bpart[NB * NCH * NI];
__device__ int   g_sidx[NB * NS];
__device__ int   g_cnt[NB];
__device__ __nv_bfloat16 g_ut_hi[NA * NI];     // [n][k]
__device__ __nv_bfloat16 g_ut_lo[NA * NI];     // [n][k]
__device__ __nv_bfloat16 g_it_hi[(size_t)NB * NS * NI];  // [b][s][k]
__device__ __nv_bfloat16 g_it_lo[(size_t)NB * NS * NI];

// ---------------------------------------------------------------------------
// PTX helpers (baseline ISA only: sm_80-class mma.sync + ldmatrix)
// ---------------------------------------------------------------------------
__device__ __forceinline__ uint32_t smem_u32(const void* p) {
    uint32_t a;
    asm("{ .reg .u64 t; cvta.to.shared.u64 t, %1; cvt.u32.u64 %0, t; }"
        : "=r"(a) : "l"(p));
    return a;
}

#define LDSM4(r, addr) \
    asm volatile("ldmatrix.sync.aligned.m8n8.x4.shared.b16 {%0,%1,%2,%3}, [%4];" \
        : "=r"((r)[0]), "=r"((r)[1]), "=r"((r)[2]), "=r"((r)[3]) : "r"(addr))

#define MMA16816(d, a, b0v, b1v) \
    asm volatile("mma.sync.aligned.m16n8k16.row.col.f32.bf16.bf16.f32 " \
        "{%0,%1,%2,%3}, {%4,%5,%6,%7}, {%8,%9}, {%0,%1,%2,%3};" \
        : "+f"((d)[0]), "+f"((d)[1]), "+f"((d)[2]), "+f"((d)[3]) \
        : "r"((a)[0]), "r"((a)[1]), "r"((a)[2]), "r"((a)[3]), \
          "r"(b0v), "r"(b1v))

__device__ __forceinline__ void split2(float x, float y,
                                       uint32_t& h, uint32_t& l) {
    __nv_bfloat162 hh = __floats2bfloat162_rn(x, y);
    const float hx = __bfloat162float(hh.x);
    const float hy = __bfloat162float(hh.y);
    __nv_bfloat162 ll = __floats2bfloat162_rn(x - hx, y - hy);
    h = *reinterpret_cast<uint32_t*>(&hh);
    l = *reinterpret_cast<uint32_t*>(&ll);
}

// ---------------------------------------------------------------------------
// Kernel 0: per-batch compaction of active s-indices
// ---------------------------------------------------------------------------
__global__ void compact_kernel(const int* __restrict__ weights)
{
    const int b = blockIdx.x;
    const int lane = threadIdx.x;
    int base = 0;
    for (int c = 0; c < NS / 32; c++) {
        const int s = c * 32 + lane;
        const int active = (weights[b * NS + s] != 0);
        const unsigned m = __ballot_sync(0xffffffffu, active);
        const int pre = __popc(m & ((1u << lane) - 1u));
        if (active) g_sidx[b * NS + base + pre] = s;
        base += __popc(m);
    }
    if (lane == 0) g_cnt[b] = base;
}

// ---------------------------------------------------------------------------
// Kernel 1: pq[b,a] = queries[b] @ W
// ---------------------------------------------------------------------------
__global__ void pq_kernel(const float* __restrict__ queries,
                          const float* __restrict__ W)
{
    const int b = blockIdx.x;
    const int a = blockIdx.y * 256 + threadIdx.x;
    __shared__ float qs[NQ];
    for (int i = threadIdx.x; i < NQ; i += 256) qs[i] = queries[b * NQ + i];
    __syncthreads();
    float acc = 0.f;
#pragma unroll 8
    for (int q = 0; q < NQ; q++) acc = fmaf(qs[q], W[(size_t)q * NA + a], acc);
    g_pq[b * NA + a] = acc;
}

// ---------------------------------------------------------------------------
// Kernel 1b: transpose + split U -> Ut hi/lo bf16 [n][k]
// ---------------------------------------------------------------------------
__global__ void transpose_kernel(const float* __restrict__ U)
{
    __shared__ float tile[32][33];
    const int n0 = blockIdx.x * 32, k0 = blockIdx.y * 32;
    const int tx = threadIdx.x, ty = threadIdx.y;  // 32 x 8
#pragma unroll
    for (int i = 0; i < 32; i += 8)
        tile[ty + i][tx] = U[(size_t)(k0 + ty + i) * NA + n0 + tx];
    __syncthreads();
#pragma unroll
    for (int i = 0; i < 32; i += 8) {
        const int n = n0 + ty + i, k = k0 + tx;
        const float a = tile[tx][ty + i];
        const __nv_bfloat16 h = __float2bfloat16(a);
        const float l = a - __bfloat162float(h);
        g_ut_hi[(size_t)n * NI + k] = h;
        g_ut_lo[(size_t)n * NI + k] = __float2bfloat16(l);
    }
}

// ---------------------------------------------------------------------------
// Kernel 1c: split items -> bf16 hi/lo (one-time; removes in-loop conversion)
// ---------------------------------------------------------------------------
__global__ void convert_items_kernel(const float* __restrict__ items)
{
    const size_t base = ((size_t)blockIdx.x * 256 + threadIdx.x) * 8;
    const float4 f0 = *(const float4*)(items + base);
    const float4 f1 = *(const float4*)(items + base + 4);
    uint4 h, l;
    split2(f0.x, f0.y, h.x, l.x);
    split2(f0.z, f0.w, h.y, l.y);
    split2(f1.x, f1.y, h.z, l.z);
    split2(f1.z, f1.w, h.w, l.w);
    *(uint4*)(g_it_hi + base) = h;
    *(uint4*)(g_it_lo + base) = l;
}

// ---------------------------------------------------------------------------
// Kernel 2 (dominant): bf16x3 split GEMM on mma.sync (HMMA) + fused epilogue.
// CTA: 128 gathered m-rows x 128 n, 8 warps (4m x 2n), BK=32,
// double-buffered smem + register prefetch (1 barrier/stage).
// Streams: ah*bh + ah*bl + al*bh into fp32 accumulators.
// ---------------------------------------------------------------------------
__global__ void __launch_bounds__(256, 1)
react_kernel(const float* __restrict__ v)
{
    extern __shared__ char smem[];
    const int b   = blockIdx.y;
    const int cnt = g_cnt[b];
    const int m0  = blockIdx.x * BMT;
    if (m0 >= cnt) return;

    const uint32_t sb = smem_u32(smem);
    const int t   = threadIdx.x;
    const int wid = t >> 5;
    const int l   = t & 31;
    const int WM  = (wid >> 1) * 32;   // warp m base
    const int WN  = (wid & 1) * 64;    // warp n base
    const int warpN = wid & 1;

    // stage pq row + v into smem (read by epilogue)
    {
        const float* __restrict__ pqg = g_pq + b * NA;
        ((float4*)(smem + OFF_PQ))[t] = ((const float4*)pqg)[t];
        ((float4*)(smem + OFF_V))[t]  = ((const float4*)v)[t];
    }

    // loader mapping: 2 threads per row, 16 bf16 each
    const int row  = t >> 1;
    const int kh16 = (t & 1) * 16;
    const uint32_t soff = (uint32_t)row * 112 + (t & 1) * 32;

    // gathered A row (clamped; duplicates idempotent)
    const int cl   = cnt - 1;
    const int arow = g_sidx[b * NS + min(m0 + row, cl)];
    const __nv_bfloat16* __restrict__ gAh =
        g_it_hi + ((size_t)b * NS + arow) * NI + kh16;
    const __nv_bfloat16* __restrict__ gAl =
        g_it_lo + ((size_t)b * NS + arow) * NI + kh16;

    // ldmatrix lane address components (within-buffer byte offsets)
    const uint32_t aSel  = (uint32_t)(l & 15);
    const uint32_t aHalf = (uint32_t)(l >> 4);
    const uint32_t aOff  = (WM + aSel) * 112 + aHalf * 16;
    const uint32_t bSel  = (uint32_t)((l & 7) + ((l >> 4) & 1) * 8);
    const uint32_t bHalf = (uint32_t)((l >> 3) & 1);
    const uint32_t bOff  = (WN + bSel) * 112 + bHalf * 16;

    float p0 = 0.f, p1 = 0.f, p2 = 0.f, p3 = 0.f;   // row partials

    for (int nt = 0; nt < NA / BNT; nt++) {
        const __nv_bfloat16* __restrict__ gBh =
            g_ut_hi + (size_t)(nt * BNT + row) * NI + kh16;
        const __nv_bfloat16* __restrict__ gBl =
            g_ut_lo + (size_t)(nt * BNT + row) * NI + kh16;

        float acc[2][8][4];
#pragma unroll
        for (int i = 0; i < 2; i++)
#pragma unroll
            for (int j = 0; j < 8; j++)
#pragma unroll
                for (int c = 0; c < 4; c++) acc[i][j][c] = 0.f;

        // prefetch stage 0 and store to buffer 0
        uint4 pAh0 = *(const uint4*)(gAh);
        uint4 pAh1 = *(const uint4*)(gAh + 8);
        uint4 pAl0 = *(const uint4*)(gAl);
        uint4 pAl1 = *(const uint4*)(gAl + 8);
        uint4 pBh0 = *(const uint4*)(gBh);
        uint4 pBh1 = *(const uint4*)(gBh + 8);
        uint4 pBl0 = *(const uint4*)(gBl);
        uint4 pBl1 = *(const uint4*)(gBl + 8);
        *(uint4*)(smem + OFF_AH + soff)      = pAh0;
        *(uint4*)(smem + OFF_AH + soff + 16) = pAh1;
        *(uint4*)(smem + OFF_AL + soff)      = pAl0;
        *(uint4*)(smem + OFF_AL + soff + 16) = pAl1;
        *(uint4*)(smem + OFF_BH + soff)      = pBh0;
        *(uint4*)(smem + OFF_BH + soff + 16) = pBh1;
        *(uint4*)(smem + OFF_BL + soff)      = pBl0;
        *(uint4*)(smem + OFF_BL + soff + 16) = pBl1;

#pragma unroll 1
        for (int ks = 0; ks < NI / BK; ks++) {
            const int last = (ks == NI / BK - 1);
            if (!last) {
                const int ko = (ks + 1) * BK;
                pAh0 = *(const uint4*)(gAh + ko);
                pAh1 = *(const uint4*)(gAh + ko + 8);
                pAl0 = *(const uint4*)(gAl + ko);
                pAl1 = *(const uint4*)(gAl + ko + 8);
                pBh0 = *(const uint4*)(gBh + ko);
                pBh1 = *(const uint4*)(gBh + ko + 8);
                pBl0 = *(const uint4*)(gBl + ko);
                pBl1 = *(const uint4*)(gBl + ko + 8);
            }
            __syncthreads();   // buffer ks&1 fully stored; compute(ks-1) done
            if (!last) {
                const uint32_t nb = ((ks + 1) & 1) * BUFSZ;
                *(uint4*)(smem + nb + OFF_AH + soff)      = pAh0;
                *(uint4*)(smem + nb + OFF_AH + soff + 16) = pAh1;
                *(uint4*)(smem + nb + OFF_AL + soff)      = pAl0;
                *(uint4*)(smem + nb + OFF_AL + soff + 16) = pAl1;
                *(uint4*)(smem + nb + OFF_BH + soff)      = pBh0;
                *(uint4*)(smem + nb + OFF_BH + soff + 16) = pBh1;
                *(uint4*)(smem + nb + OFF_BL + soff)      = pBl0;
                *(uint4*)(smem + nb + OFF_BL + soff + 16) = pBl1;
            }

            const uint32_t cb = (ks & 1) * BUFSZ;
            const uint32_t aBaseH = sb + cb + OFF_AH + aOff;
            const uint32_t aBaseL = sb + cb + OFF_AL + aOff;
            const uint32_t bBaseH = sb + cb + OFF_BH + bOff;
            const uint32_t bBaseL = sb + cb + OFF_BL + bOff;

#pragma unroll
            for (int s = 0; s < 2; s++) {   // two k16 steps
                uint32_t Ah[2][4], Al[2][4], Bh[4][4], Bl[4][4];
#pragma unroll
                for (int i = 0; i < 2; i++) {
                    LDSM4(Ah[i], aBaseH + i * 1792 + s * 32);
                    LDSM4(Al[i], aBaseL + i * 1792 + s * 32);
                }
#pragma unroll
                for (int g = 0; g < 4; g++) {
                    LDSM4(Bh[g], bBaseH + g * 1792 + s * 32);
                    LDSM4(Bl[g], bBaseL + g * 1792 + s * 32);
                }
#pragma unroll
                for (int g = 0; g < 4; g++)
#pragma unroll
                    for (int h = 0; h < 2; h++) {
                        const int j = 2 * g + h;
#pragma unroll
                        for (int i = 0; i < 2; i++) {
                            MMA16816(acc[i][j], Ah[i], Bh[g][2 * h], Bh[g][2 * h + 1]);
                            MMA16816(acc[i][j], Ah[i], Bl[g][2 * h], Bl[g][2 * h + 1]);
                            MMA16816(acc[i][j], Al[i], Bh[g][2 * h], Bh[g][2 * h + 1]);
                        }
                    }
            }
        }

        // fused epilogue for this n-tile: tanh + dot(v) into row partials
#pragma unroll
        for (int j = 0; j < 8; j++) {
            const int ng = nt * BNT + WN + j * 8 + (l & 3) * 2;
            const float2 pq2 = *(const float2*)(smem + OFF_PQ + ng * 4);
            const float2 v2  = *(const float2*)(smem + OFF_V  + ng * 4);
            p0 += tanhf(acc[0][j][0] + pq2.x) * v2.x
                + tanhf(acc[0][j][1] + pq2.y) * v2.y;
            p1 += tanhf(acc[0][j][2] + pq2.x) * v2.x
                + tanhf(acc[0][j][3] + pq2.y) * v2.y;
            p2 += tanhf(acc[1][j][0] + pq2.x) * v2.x
                + tanhf(acc[1][j][1] + pq2.y) * v2.y;
            p3 += tanhf(acc[1][j][2] + pq2.x) * v2.x
                + tanhf(acc[1][j][3] + pq2.y) * v2.y;
        }
    }

    // quad reduce (lanes sharing l>>2), then cross-warpN reduce via smem
#pragma unroll
    for (int d = 1; d <= 2; d <<= 1) {
        p0 += __shfl_xor_sync(0xffffffffu, p0, d);
        p1 += __shfl_xor_sync(0xffffffffu, p1, d);
        p2 += __shfl_xor_sync(0xffffffffu, p2, d);
        p3 += __shfl_xor_sync(0xffffffffu, p3, d);
    }
    float* red = (float*)(smem + OFF_RED);
    __syncthreads();   // done with operand smem before reusing barrier slot
    if ((l & 3) == 0) {
        const int r0 = WM + (l >> 2);
        red[warpN * 128 + r0]      = p0;
        red[warpN * 128 + r0 + 8]  = p1;
        red[warpN * 128 + r0 + 16] = p2;
        red[warpN * 128 + r0 + 24] = p3;
    }
    __syncthreads();
    if (t < 128) {
        const float sum = red[t] + red[128 + t];
        const int s = g_sidx[b * NS + min(m0 + t, cl)];
        g_react[b * NS + s] = sum;   // clamped duplicates write identical values
    }
}

// ---------------------------------------------------------------------------
// Kernel 3: masked softmax over S per batch; writes scores into out.
// ---------------------------------------------------------------------------
__global__ void softmax_kernel(const int* __restrict__ weights,
                               float* __restrict__ out)
{
    const int b = blockIdx.x;
    const int t = threadIdx.x;
    __shared__ float sm[256];

    float vals[NS / 256];
    float mx = -INFINITY;
#pragma unroll
    for (int r = 0; r < NS / 256; r++) {
        const int s = t + r * 256;
        const float x = (weights[b * NS + s] == 0) ? -INFINITY
                                                   : g_react[b * NS + s];
        vals[r] = x;
        mx = fmaxf(mx, x);
    }
    sm[t] = mx; __syncthreads();
    for (int off = 128; off > 0; off >>= 1) {
        if (t < off) sm[t] = fmaxf(sm[t], sm[t + off]);
        __syncthreads();
    }
    mx = sm[0];
    __syncthreads();

    float sum = 0.f;
#pragma unroll
    for (int r = 0; r < NS / 256; r++) {
        vals[r] = expf(vals[r] - mx);
        sum += vals[r];
    }
    sm[t] = sum; __syncthreads();
    for (int off = 128; off > 0; off >>= 1) {
        if (t < off) sm[t] += sm[t + off];
        __syncthreads();
    }
    const float inv = 1.f / sm[0];

    float* scores = out + NB * NI + (size_t)b * NS;
#pragma unroll
    for (int r = 0; r < NS / 256; r++)
        scores[t + r * 256] = vals[r] * inv;
}

// ---------------------------------------------------------------------------
// Kernel 4a: blended partials per (b, s-chunk)
// ---------------------------------------------------------------------------
__global__ void blend_partial_kernel(const float* __restrict__ items,
                                     const float* __restrict__ out)
{
    const int b  = blockIdx.x;
    const int ch = blockIdx.y;
    const int s0 = ch * (NS / NCH);
    const float* __restrict__ scores = out + NB * NI + (size_t)b * NS;
    const float* __restrict__ base   = items + (size_t)b * NS * NI;
    const int i = threadIdx.x * 4;

    float4 acc = make_float4(0.f, 0.f, 0.f, 0.f);
    for (int s = 0; s < NS / NCH; s++) {
        const float w = scores[s0 + s];
        if (w != 0.f) {
            const float4 x = *(const float4*)(base + (size_t)(s0 + s) * NI + i);
            acc.x = fmaf(w, x.x, acc.x);
            acc.y = fmaf(w, x.y, acc.y);
            acc.z = fmaf(w, x.z, acc.z);
            acc.w = fmaf(w, x.w, acc.w);
        }
    }
    *(float4*)(g_bpart + (size_t)(b * NCH + ch) * NI + i) = acc;
}

// ---------------------------------------------------------------------------
// Kernel 4b: reduce partials -> blended
// ---------------------------------------------------------------------------
__global__ void blend_reduce_kernel(float* __restrict__ out)
{
    const int b = blockIdx.x;
    const int i = threadIdx.x * 4;
    float4 acc = make_float4(0.f, 0.f, 0.f, 0.f);
    for (int c = 0; c < NCH; c++) {
        const float4 x = *(const float4*)(g_bpart + (size_t)(b * NCH + c) * NI + i);
        acc.x += x.x; acc.y += x.y; acc.z += x.z; acc.w += x.w;
    }
    *(float4*)(out + (size_t)b * NI + i) = acc;
}

// ---------------------------------------------------------------------------
extern "C" void kernel_launch(void* const* d_in, const int* in_sizes, int n_in,
                              void* d_out, int out_size)
{
    const float* queries = (const float*)d_in[0];
    const float* items   = (const float*)d_in[1];
    const int*   weights = (const int*)  d_in[2];
    const float* W       = (const float*)d_in[3];
    const float* U       = (const float*)d_in[4];
    const float* v       = (const float*)d_in[5];
    float* out = (float*)d_out;   // [B*I blended | B*S scores]

    static int attr_set = 0;
    if (!attr_set) {
        cudaFuncSetAttribute(react_kernel,
                             cudaFuncAttributeMaxDynamicSharedMemorySize, SM_TOTAL);
        attr_set = 1;
    }

    compact_kernel<<<NB, 32>>>(weights);
    pq_kernel<<<dim3(NB, NA / 256), 256>>>(queries, W);
    transpose_kernel<<<dim3(NA / 32, NI / 32), dim3(32, 8)>>>(U);
    convert_items_kernel<<<(int)(((size_t)NB * NS * NI) / (256 * 8)), 256>>>(items);
    react_kernel<<<dim3(NS / BMT, NB), 256, SM_TOTAL>>>(v);
    softmax_kernel<<<NB, 256>>>(weights, out);
    blend_partial_kernel<<<dim3(NB, NCH), 256>>>(items, out);
    blend_reduce_kernel<<<NB, 256>>>(out);
}

// round 5
// speedup vs baseline: 9.1557x; 2.1344x over previous
#include <cuda_runtime.h>
#include <cuda_fp16.h>
#include <math.h>
#include <stdint.h>

#define NB 32
#define NS 2048
#define NQ 1024
#define NI 1024
#define NA 1024
#define NCH 16

// ---- react tiling ----
#define BMT 256                 // CTA m tile (1-wave grid)
#define BNT 128                 // CTA n tile (8 passes)
#define BK  32                  // k per stage
#define NSTG 4                  // cp.async pipeline depth
#define PITCHB 80               // smem row pitch bytes (64B data; conflict-free ldmatrix)
#define STG_A 0
#define STG_B (256 * PITCHB)            // 20480
#define STG_SZ (STG_B + 128 * PITCHB)   // 30720
#define OFF_PQ (NSTG * STG_SZ)          // 122880
#define OFF_V  (OFF_PQ + 4096)
#define OFF_RED (OFF_V + 4096)
#define SM_TOTAL (OFF_RED + 2048)       // 133120 bytes

// scratch (device globals: allocation-free per harness rules)
__device__ float g_pq[NB * NA];
__device__ float g_react[NB * NS];
__device__ float g_bpart[NB * NCH * NI];
__device__ int   g_sidx[NB * NS];
__device__ int   g_cnt[NB];
__device__ __half g_ut16[NA * NI];                // [n][k] fp16
__device__ __half g_it16[(size_t)NB * NS * NI];   // [b][j][k] fp16, gather-compacted

// ---------------------------------------------------------------------------
// PTX helpers (baseline ISA: mma.sync f16, ldmatrix, cp.async — all sm_80)
// ---------------------------------------------------------------------------
__device__ __forceinline__ uint32_t smem_u32(const void* p) {
    uint32_t a;
    asm("{ .reg .u64 t; cvta.to.shared.u64 t, %1; cvt.u32.u64 %0, t; }"
        : "=r"(a) : "l"(p));
    return a;
}

#define LDSM4(r, addr) \
    asm volatile("ldmatrix.sync.aligned.m8n8.x4.shared.b16 {%0,%1,%2,%3}, [%4];" \
        : "=r"((r)[0]), "=r"((r)[1]), "=r"((r)[2]), "=r"((r)[3]) : "r"(addr))

#define MMAF16(d, a, b0v, b1v) \
    asm volatile("mma.sync.aligned.m16n8k16.row.col.f32.f16.f16.f32 " \
        "{%0,%1,%2,%3}, {%4,%5,%6,%7}, {%8,%9}, {%0,%1,%2,%3};" \
        : "+f"((d)[0]), "+f"((d)[1]), "+f"((d)[2]), "+f"((d)[3]) \
        : "r"((a)[0]), "r"((a)[1]), "r"((a)[2]), "r"((a)[3]), \
          "r"(b0v), "r"(b1v))

#define CP16(dst, src) \
    asm volatile("cp.async.cg.shared.global [%0], [%1], 16;" \
        :: "r"(dst), "l"(src) : "memory")
#define CP_COMMIT() asm volatile("cp.async.commit_group;" ::: "memory")
#define CP_WAIT2()  asm volatile("cp.async.wait_group 2;" ::: "memory")

// ---------------------------------------------------------------------------
// Kernel 0: per-batch compaction of active s-indices
// ---------------------------------------------------------------------------
__global__ void compact_kernel(const int* __restrict__ weights)
{
    const int b = blockIdx.x;
    const int lane = threadIdx.x;
    int base = 0;
    for (int c = 0; c < NS / 32; c++) {
        const int s = c * 32 + lane;
        const int active = (weights[b * NS + s] != 0);
        const unsigned m = __ballot_sync(0xffffffffu, active);
        const int pre = __popc(m & ((1u << lane) - 1u));
        if (active) g_sidx[b * NS + base + pre] = s;
        base += __popc(m);
    }
    if (lane == 0) g_cnt[b] = base;
}

// ---------------------------------------------------------------------------
// Kernel 1: pq[b,a] = queries[b] @ W
// ---------------------------------------------------------------------------
__global__ void pq_kernel(const float* __restrict__ queries,
                          const float* __restrict__ W)
{
    const int b = blockIdx.x;
    const int a = blockIdx.y * 256 + threadIdx.x;
    __shared__ float qs[NQ];
    for (int i = threadIdx.x; i < NQ; i += 256) qs[i] = queries[b * NQ + i];
    __syncthreads();
    float acc = 0.f;
#pragma unroll 8
    for (int q = 0; q < NQ; q++) acc = fmaf(qs[q], W[(size_t)q * NA + a], acc);
    g_pq[b * NA + a] = acc;
}

// ---------------------------------------------------------------------------
// Kernel 1b: transpose U -> Ut fp16 [n][k]
// ---------------------------------------------------------------------------
__global__ void transpose_kernel(const float* __restrict__ U)
{
    __shared__ float tile[32][33];
    const int n0 = blockIdx.x * 32, k0 = blockIdx.y * 32;
    const int tx = threadIdx.x, ty = threadIdx.y;  // 32 x 8
#pragma unroll
    for (int i = 0; i < 32; i += 8)
        tile[ty + i][tx] = U[(size_t)(k0 + ty + i) * NA + n0 + tx];
    __syncthreads();
#pragma unroll
    for (int i = 0; i < 32; i += 8) {
        const int n = n0 + ty + i, k = k0 + tx;
        g_ut16[(size_t)n * NI + k] = __float2half(tile[tx][ty + i]);
    }
}

// ---------------------------------------------------------------------------
// Kernel 1c: gather-compact items -> fp16 (only active rows, ~half the work)
// ---------------------------------------------------------------------------
__global__ void convert_items_kernel(const float* __restrict__ items)
{
    const int b = blockIdx.y;
    const int j = blockIdx.x * 2 + (threadIdx.x >> 7);
    if (j >= g_cnt[b]) return;
    const int s = g_sidx[b * NS + j];
    const int off = (threadIdx.x & 127) * 8;
    const float* src = items + ((size_t)b * NS + s) * NI + off;
    const float4 f0 = *(const float4*)(src);
    const float4 f1 = *(const float4*)(src + 4);
    __half2 h0 = __floats2half2_rn(f0.x, f0.y);
    __half2 h1 = __floats2half2_rn(f0.z, f0.w);
    __half2 h2 = __floats2half2_rn(f1.x, f1.y);
    __half2 h3 = __floats2half2_rn(f1.z, f1.w);
    uint4 o;
    o.x = *reinterpret_cast<uint32_t*>(&h0);
    o.y = *reinterpret_cast<uint32_t*>(&h1);
    o.z = *reinterpret_cast<uint32_t*>(&h2);
    o.w = *reinterpret_cast<uint32_t*>(&h3);
    *(uint4*)(g_it16 + ((size_t)b * NS + j) * NI + off) = o;
}

// ---------------------------------------------------------------------------
// Kernel 2 (dominant): single-stream fp16 GEMM on mma.sync + fused epilogue.
// CTA: 256 compacted m-rows x 128 n per pass (8 passes), 8 warps 64x64 tiles,
// 4-stage cp.async pipeline, BK=32.
// ---------------------------------------------------------------------------
__global__ void __launch_bounds__(256, 1)
react_kernel(const float* __restrict__ v)
{
    extern __shared__ char smem[];
    const int b   = blockIdx.y;
    const int cnt = g_cnt[b];
    const int m0  = blockIdx.x * BMT;
    if (m0 >= cnt) return;

    const uint32_t sb = smem_u32(smem);
    const int t   = threadIdx.x;
    const int wid = t >> 5;
    const int l   = t & 31;
    const int WM  = (wid >> 1) * 64;
    const int WN  = (wid & 1) * 64;

    // stage pq + v (full 1024 each)
    {
        const float* __restrict__ pqg = g_pq + b * NA;
        ((float4*)(smem + OFF_PQ))[t] = ((const float4*)pqg)[t];
        ((float4*)(smem + OFF_V))[t]  = ((const float4*)v)[t];
    }

    // loader mapping: 6 cp.async(16B) per stage per thread
    const int rA = t >> 2;                // 0..63
    const uint32_t q16 = (t & 3) * 16;
    const char* aBase = (const char*)(g_it16 + ((size_t)b * NS + m0 + rA) * NI) + q16;
    const char* bBase = (const char*)(g_ut16 + (size_t)rA * NI) + q16;
    const uint32_t dA = sb + STG_A + rA * PITCHB + q16;
    const uint32_t dB = sb + STG_B + rA * PITCHB + q16;
    const size_t R64 = (size_t)64 * NI * 2;   // 64 rows in bytes

    // ldmatrix lane offsets (within stage)
    const uint32_t aOff = STG_A + (WM + (l & 15)) * PITCHB + (l >> 4) * 16;
    const uint32_t bOff = STG_B + (WN + (l & 7) + ((l >> 4) & 1) * 8) * PITCHB
                          + ((l >> 3) & 1) * 16;

    float acc[4][8][4];
    float p8[8];
#pragma unroll
    for (int i = 0; i < 8; i++) p8[i] = 0.f;

    // pipeline prologue: stages 0..2
#pragma unroll
    for (int p = 0; p < NSTG - 1; p++) {
        const uint32_t soff = p * STG_SZ;
        const size_t kb = (size_t)(p & 31) * 64;   // nt=0 for p<32
        const char* pa = aBase + kb;
        const char* pb = bBase + kb;
        CP16(dA + soff,               pa);
        CP16(dA + soff +  64 * PITCHB, pa + R64);
        CP16(dA + soff + 128 * PITCHB, pa + 2 * R64);
        CP16(dA + soff + 192 * PITCHB, pa + 3 * R64);
        CP16(dB + soff,               pb);
        CP16(dB + soff +  64 * PITCHB, pb + R64);
        CP_COMMIT();
    }

#pragma unroll 1
    for (int sg = 0; sg < 256; sg++) {
        const int ks = sg & 31;
        const int nt = sg >> 5;
        const uint32_t sbase = (sg & (NSTG - 1)) * STG_SZ;

        CP_WAIT2();
        __syncthreads();

        // issue stage sg+3 (safe: all warps past compute(sg-1))
        if (sg + NSTG - 1 < 256) {
            const int s2  = sg + NSTG - 1;
            const int ks2 = s2 & 31, nt2 = s2 >> 5;
            const uint32_t soff = (s2 & (NSTG - 1)) * STG_SZ;
            const size_t kb = (size_t)ks2 * 64;
            const char* pa = aBase + kb;
            const char* pb = bBase + (size_t)nt2 * 128 * NI * 2 + kb;
            CP16(dA + soff,               pa);
            CP16(dA + soff +  64 * PITCHB, pa + R64);
            CP16(dA + soff + 128 * PITCHB, pa + 2 * R64);
            CP16(dA + soff + 192 * PITCHB, pa + 3 * R64);
            CP16(dB + soff,               pb);
            CP16(dB + soff +  64 * PITCHB, pb + R64);
            CP_COMMIT();
        }

        if (ks == 0) {
#pragma unroll
            for (int i = 0; i < 4; i++)
#pragma unroll
                for (int j = 0; j < 8; j++)
#pragma unroll
                    for (int c = 0; c < 4; c++) acc[i][j][c] = 0.f;
        }

#pragma unroll
        for (int s = 0; s < 2; s++) {   // two k16 steps
            uint32_t Ah[4][4];
#pragma unroll
            for (int i = 0; i < 4; i++)
                LDSM4(Ah[i], sb + sbase + aOff + i * 1280 + s * 32);
#pragma unroll
            for (int g = 0; g < 4; g++) {
                uint32_t Bh[4];
                LDSM4(Bh, sb + sbase + bOff + g * 1280 + s * 32);
#pragma unroll
                for (int i = 0; i < 4; i++) {
                    MMAF16(acc[i][2 * g],     Ah[i], Bh[0], Bh[1]);
                    MMAF16(acc[i][2 * g + 1], Ah[i], Bh[2], Bh[3]);
                }
            }
        }

        if (ks == 31) {   // pass epilogue: tanh + dot(v) into row partials
#pragma unroll
            for (int j = 0; j < 8; j++) {
                const int n = nt * BNT + WN + j * 8 + (l & 3) * 2;
                const float2 pq2 = *(const float2*)(smem + OFF_PQ + n * 4);
                const float2 v2  = *(const float2*)(smem + OFF_V  + n * 4);
#pragma unroll
                for (int i = 0; i < 4; i++) {
#pragma unroll
                    for (int h = 0; h < 2; h++) {
                        p8[i * 2 + h] += tanhf(acc[i][j][h * 2]     + pq2.x) * v2.x
                                       + tanhf(acc[i][j][h * 2 + 1] + pq2.y) * v2.y;
                    }
                }
            }
        }
    }

    // quad reduce (columns within quad), then cross-warpN reduce via smem
#pragma unroll
    for (int pi = 0; pi < 8; pi++) {
        float x = p8[pi];
        x += __shfl_xor_sync(0xffffffffu, x, 1);
        x += __shfl_xor_sync(0xffffffffu, x, 2);
        p8[pi] = x;
    }
    float* red = (float*)(smem + OFF_RED);
    if ((l & 3) == 0) {
#pragma unroll
        for (int pi = 0; pi < 8; pi++) {
            const int row = WM + (pi >> 1) * 16 + (pi & 1) * 8 + (l >> 2);
            red[(wid & 1) * 256 + row] = p8[pi];
        }
    }
    __syncthreads();
    if (m0 + t < cnt) {
        const float sum = red[t] + red[256 + t];
        g_react[b * NS + g_sidx[b * NS + m0 + t]] = sum;
    }
}

// ---------------------------------------------------------------------------
// Kernel 3: masked softmax over S per batch; writes scores into out.
// ---------------------------------------------------------------------------
__global__ void softmax_kernel(const int* __restrict__ weights,
                               float* __restrict__ out)
{
    const int b = blockIdx.x;
    const int t = threadIdx.x;
    __shared__ float sm[256];

    float vals[NS / 256];
    float mx = -INFINITY;
#pragma unroll
    for (int r = 0; r < NS / 256; r++) {
        const int s = t + r * 256;
        const float x = (weights[b * NS + s] == 0) ? -INFINITY
                                                   : g_react[b * NS + s];
        vals[r] = x;
        mx = fmaxf(mx, x);
    }
    sm[t] = mx; __syncthreads();
    for (int off = 128; off > 0; off >>= 1) {
        if (t < off) sm[t] = fmaxf(sm[t], sm[t + off]);
        __syncthreads();
    }
    mx = sm[0];
    __syncthreads();

    float sum = 0.f;
#pragma unroll
    for (int r = 0; r < NS / 256; r++) {
        vals[r] = expf(vals[r] - mx);
        sum += vals[r];
    }
    sm[t] = sum; __syncthreads();
    for (int off = 128; off > 0; off >>= 1) {
        if (t < off) sm[t] += sm[t + off];
        __syncthreads();
    }
    const float inv = 1.f / sm[0];

    float* scores = out + NB * NI + (size_t)b * NS;
#pragma unroll
    for (int r = 0; r < NS / 256; r++)
        scores[t + r * 256] = vals[r] * inv;
}

// ---------------------------------------------------------------------------
// Kernel 4a: blended partials per (b, s-chunk)
// ---------------------------------------------------------------------------
__global__ void blend_partial_kernel(const float* __restrict__ items,
                                     const float* __restrict__ out)
{
    const int b  = blockIdx.x;
    const int ch = blockIdx.y;
    const int s0 = ch * (NS / NCH);
    const float* __restrict__ scores = out + NB * NI + (size_t)b * NS;
    const float* __restrict__ base   = items + (size_t)b * NS * NI;
    const int i = threadIdx.x * 4;

    float4 acc = make_float4(0.f, 0.f, 0.f, 0.f);
    for (int s = 0; s < NS / NCH; s++) {
        const float w = scores[s0 + s];
        if (w != 0.f) {
            const float4 x = *(const float4*)(base + (size_t)(s0 + s) * NI + i);
            acc.x = fmaf(w, x.x, acc.x);
            acc.y = fmaf(w, x.y, acc.y);
            acc.z = fmaf(w, x.z, acc.z);
            acc.w = fmaf(w, x.w, acc.w);
        }
    }
    *(float4*)(g_bpart + (size_t)(b * NCH + ch) * NI + i) = acc;
}

// ---------------------------------------------------------------------------
// Kernel 4b: reduce partials -> blended
// ---------------------------------------------------------------------------
__global__ void blend_reduce_kernel(float* __restrict__ out)
{
    const int b = blockIdx.x;
    const int i = threadIdx.x * 4;
    float4 acc = make_float4(0.f, 0.f, 0.f, 0.f);
    for (int c = 0; c < NCH; c++) {
        const float4 x = *(const float4*)(g_bpart + (size_t)(b * NCH + c) * NI + i);
        acc.x += x.x; acc.y += x.y; acc.z += x.z; acc.w += x.w;
    }
    *(float4*)(out + (size_t)b * NI + i) = acc;
}

// ---------------------------------------------------------------------------
extern "C" void kernel_launch(void* const* d_in, const int* in_sizes, int n_in,
                              void* d_out, int out_size)
{
    const float* queries = (const float*)d_in[0];
    const float* items   = (const float*)d_in[1];
    const int*   weights = (const int*)  d_in[2];
    const float* W       = (const float*)d_in[3];
    const float* U       = (const float*)d_in[4];
    const float* v       = (const float*)d_in[5];
    float* out = (float*)d_out;   // [B*I blended | B*S scores]

    static int attr_set = 0;
    if (!attr_set) {
        cudaFuncSetAttribute(react_kernel,
                             cudaFuncAttributeMaxDynamicSharedMemorySize, SM_TOTAL);
        attr_set = 1;
    }

    compact_kernel<<<NB, 32>>>(weights);
    pq_kernel<<<dim3(NB, NA / 256), 256>>>(queries, W);
    transpose_kernel<<<dim3(NA / 32, NI / 32), dim3(32, 8)>>>(U);
    convert_items_kernel<<<dim3(NS / 2, NB), 256>>>(items);
    react_kernel<<<dim3(NS / BMT, NB), 256, SM_TOTAL>>>(v);
    softmax_kernel<<<NB, 256>>>(weights, out);
    blend_partial_kernel<<<dim3(NB, NCH), 256>>>(items, out);
    blend_reduce_kernel<<<NB, 256>>>(out);
}

// round 6
// speedup vs baseline: 9.8308x; 1.0737x over previous
#include <cuda_runtime.h>
#include <cuda_fp16.h>
#include <math.h>
#include <stdint.h>

#define NB 32
#define NS 2048
#define NQ 1024
#define NI 1024
#define NA 1024
#define NCH 16

// ---- react tiling ----
#define BMT 256                 // CTA m tile (1-wave grid)
#define BNT 128                 // CTA n tile (8 passes)
#define BK  32                  // k per stage
#define NSTG 4                  // cp.async pipeline depth
#define PITCHB 80               // smem row pitch bytes (64B data; conflict-free ldmatrix)
#define STG_A 0
#define STG_B (256 * PITCHB)            // 20480
#define STG_SZ (STG_B + 128 * PITCHB)   // 30720
#define OFF_PQ (NSTG * STG_SZ)          // 122880
#define OFF_V  (OFF_PQ + 4096)
#define OFF_RED (OFF_V + 4096)
#define SM_TOTAL (OFF_RED + 2048)       // 133120 bytes

// scratch (device globals: allocation-free per harness rules)
__device__ float g_pq[NB * NA];
__device__ float g_react[NB * NS];
__device__ float g_bpart[NB * NCH * NI];
__device__ int   g_sidx[NB * NS];
__device__ int   g_cnt[NB];
__device__ __half g_ut16[NA * NI];                // [n][k] fp16
__device__ __half g_it16[(size_t)NB * NS * NI];   // [b][j][k] fp16, gather-compacted

// ---------------------------------------------------------------------------
// PTX helpers (baseline ISA: mma.sync f16, ldmatrix, cp.async — all sm_80)
// ---------------------------------------------------------------------------
__device__ __forceinline__ uint32_t smem_u32(const void* p) {
    uint32_t a;
    asm("{ .reg .u64 t; cvta.to.shared.u64 t, %1; cvt.u32.u64 %0, t; }"
        : "=r"(a) : "l"(p));
    return a;
}

#define LDSM4(r, addr) \
    asm volatile("ldmatrix.sync.aligned.m8n8.x4.shared.b16 {%0,%1,%2,%3}, [%4];" \
        : "=r"((r)[0]), "=r"((r)[1]), "=r"((r)[2]), "=r"((r)[3]) : "r"(addr))

#define MMAF16(d, a, b0v, b1v) \
    asm volatile("mma.sync.aligned.m16n8k16.row.col.f32.f16.f16.f32 " \
        "{%0,%1,%2,%3}, {%4,%5,%6,%7}, {%8,%9}, {%0,%1,%2,%3};" \
        : "+f"((d)[0]), "+f"((d)[1]), "+f"((d)[2]), "+f"((d)[3]) \
        : "r"((a)[0]), "r"((a)[1]), "r"((a)[2]), "r"((a)[3]), \
          "r"(b0v), "r"(b1v))

#define CP16(dst, src) \
    asm volatile("cp.async.cg.shared.global [%0], [%1], 16;" \
        :: "r"(dst), "l"(src) : "memory")
#define CP_COMMIT() asm volatile("cp.async.commit_group;" ::: "memory")
#define CP_WAIT2()  asm volatile("cp.async.wait_group 2;" ::: "memory")

// ---------------------------------------------------------------------------
// Kernel 0: per-batch compaction of active s-indices
// ---------------------------------------------------------------------------
__global__ void compact_kernel(const int* __restrict__ weights)
{
    const int b = blockIdx.x;
    const int lane = threadIdx.x;
    int base = 0;
    for (int c = 0; c < NS / 32; c++) {
        const int s = c * 32 + lane;
        const int active = (weights[b * NS + s] != 0);
        const unsigned m = __ballot_sync(0xffffffffu, active);
        const int pre = __popc(m & ((1u << lane) - 1u));
        if (active) g_sidx[b * NS + base + pre] = s;
        base += __popc(m);
    }
    if (lane == 0) g_cnt[b] = base;
}

// ---------------------------------------------------------------------------
// Kernel 1: pq[b,a] = queries[b] @ W
// ---------------------------------------------------------------------------
__global__ void pq_kernel(const float* __restrict__ queries,
                          const float* __restrict__ W)
{
    const int b = blockIdx.x;
    const int a = blockIdx.y * 256 + threadIdx.x;
    __shared__ float qs[NQ];
    for (int i = threadIdx.x; i < NQ; i += 256) qs[i] = queries[b * NQ + i];
    __syncthreads();
    float acc = 0.f;
#pragma unroll 8
    for (int q = 0; q < NQ; q++) acc = fmaf(qs[q], W[(size_t)q * NA + a], acc);
    g_pq[b * NA + a] = acc;
}

// ---------------------------------------------------------------------------
// Kernel 1b: transpose U -> Ut fp16 [n][k]
// ---------------------------------------------------------------------------
__global__ void transpose_kernel(const float* __restrict__ U)
{
    __shared__ float tile[32][33];
    const int n0 = blockIdx.x * 32, k0 = blockIdx.y * 32;
    const int tx = threadIdx.x, ty = threadIdx.y;  // 32 x 8
#pragma unroll
    for (int i = 0; i < 32; i += 8)
        tile[ty + i][tx] = U[(size_t)(k0 + ty + i) * NA + n0 + tx];
    __syncthreads();
#pragma unroll
    for (int i = 0; i < 32; i += 8) {
        const int n = n0 + ty + i, k = k0 + tx;
        g_ut16[(size_t)n * NI + k] = __float2half(tile[tx][ty + i]);
    }
}

// ---------------------------------------------------------------------------
// Kernel 1c: gather-compact items -> fp16 (active rows; 16 elems/thread MLP)
// ---------------------------------------------------------------------------
__global__ void convert_items_kernel(const float* __restrict__ items)
{
    const int b = blockIdx.y;
    const int j = blockIdx.x * 4 + (threadIdx.x >> 6);
    if (j >= g_cnt[b]) return;
    const int s = g_sidx[b * NS + j];
    const int off = (threadIdx.x & 63) * 16;
    const float* src = items + ((size_t)b * NS + s) * NI + off;
    const float4 f0 = *(const float4*)(src);
    const float4 f1 = *(const float4*)(src + 4);
    const float4 f2 = *(const float4*)(src + 8);
    const float4 f3 = *(const float4*)(src + 12);
    __half2 h0 = __floats2half2_rn(f0.x, f0.y);
    __half2 h1 = __floats2half2_rn(f0.z, f0.w);
    __half2 h2 = __floats2half2_rn(f1.x, f1.y);
    __half2 h3 = __floats2half2_rn(f1.z, f1.w);
    __half2 h4 = __floats2half2_rn(f2.x, f2.y);
    __half2 h5 = __floats2half2_rn(f2.z, f2.w);
    __half2 h6 = __floats2half2_rn(f3.x, f3.y);
    __half2 h7 = __floats2half2_rn(f3.z, f3.w);
    uint4 o0, o1;
    o0.x = *reinterpret_cast<uint32_t*>(&h0);
    o0.y = *reinterpret_cast<uint32_t*>(&h1);
    o0.z = *reinterpret_cast<uint32_t*>(&h2);
    o0.w = *reinterpret_cast<uint32_t*>(&h3);
    o1.x = *reinterpret_cast<uint32_t*>(&h4);
    o1.y = *reinterpret_cast<uint32_t*>(&h5);
    o1.z = *reinterpret_cast<uint32_t*>(&h6);
    o1.w = *reinterpret_cast<uint32_t*>(&h7);
    __half* dst = g_it16 + ((size_t)b * NS + j) * NI + off;
    *(uint4*)(dst) = o0;
    *(uint4*)(dst + 8) = o1;
}

// ---------------------------------------------------------------------------
// Kernel 2 (dominant): single-stream fp16 GEMM on mma.sync + fused epilogue.
// CTA: 256 compacted m-rows x 128 n per pass (8 passes), 8 warps 64x64 tiles,
// 4-stage cp.async pipeline, BK=32. Epilogue hoisted out of the stage loop.
// ---------------------------------------------------------------------------
__global__ void __launch_bounds__(256, 1)
react_kernel(const float* __restrict__ v)
{
    extern __shared__ char smem[];
    const int b   = blockIdx.y;
    const int cnt = g_cnt[b];
    const int m0  = blockIdx.x * BMT;
    if (m0 >= cnt) return;

    const uint32_t sb = smem_u32(smem);
    const int t   = threadIdx.x;
    const int wid = t >> 5;
    const int l   = t & 31;
    const int WM  = (wid >> 1) * 64;
    const int WN  = (wid & 1) * 64;

    // stage pq + v (full 1024 each)
    {
        const float* __restrict__ pqg = g_pq + b * NA;
        ((float4*)(smem + OFF_PQ))[t] = ((const float4*)pqg)[t];
        ((float4*)(smem + OFF_V))[t]  = ((const float4*)v)[t];
    }

    // loader mapping: 6 cp.async(16B) per stage per thread
    const int rA = t >> 2;                // 0..63
    const uint32_t q16 = (t & 3) * 16;
    const char* aBase = (const char*)(g_it16 + ((size_t)b * NS + m0 + rA) * NI) + q16;
    const char* bBase = (const char*)(g_ut16 + (size_t)rA * NI) + q16;
    const uint32_t dA = sb + STG_A + rA * PITCHB + q16;
    const uint32_t dB = sb + STG_B + rA * PITCHB + q16;
    const size_t R64  = (size_t)64 * NI * 2;    // 64 rows in bytes
    const size_t NT_B = (size_t)128 * NI * 2;   // one 128-n B panel in bytes

    // ldmatrix lane offsets (within stage)
    const uint32_t aOff = STG_A + (WM + (l & 15)) * PITCHB + (l >> 4) * 16;
    const uint32_t bOff = STG_B + (WN + (l & 7) + ((l >> 4) & 1) * 8) * PITCHB
                          + ((l >> 3) & 1) * 16;

    float acc[4][8][4];
    float p8[8];
#pragma unroll
    for (int i = 0; i < 8; i++) p8[i] = 0.f;

    // pipeline prologue: stages 0..2 (all nt=0)
#pragma unroll
    for (int p = 0; p < NSTG - 1; p++) {
        const uint32_t soff = p * STG_SZ;
        const size_t kb = (size_t)p * 64;
        const char* pa = aBase + kb;
        const char* pb = bBase + kb;
        CP16(dA + soff,                pa);
        CP16(dA + soff +  64 * PITCHB, pa + R64);
        CP16(dA + soff + 128 * PITCHB, pa + 2 * R64);
        CP16(dA + soff + 192 * PITCHB, pa + 3 * R64);
        CP16(dB + soff,                pb);
        CP16(dB + soff +  64 * PITCHB, pb + R64);
        CP_COMMIT();
    }

#pragma unroll 1
    for (int nt = 0; nt < NA / BNT; nt++) {
#pragma unroll
        for (int i = 0; i < 4; i++)
#pragma unroll
            for (int j = 0; j < 8; j++)
#pragma unroll
                for (int c = 0; c < 4; c++) acc[i][j][c] = 0.f;

#pragma unroll 4
        for (int ks = 0; ks < 32; ks++) {
            const int sg = nt * 32 + ks;
            const uint32_t sbase = (uint32_t)(sg & (NSTG - 1)) * STG_SZ;

            CP_WAIT2();
            __syncthreads();

            // issue stage sg+3
            const int s2 = sg + NSTG - 1;
            if (s2 < 256) {
                const int ks2 = s2 & 31, nt2 = s2 >> 5;
                const uint32_t soff = (uint32_t)(s2 & (NSTG - 1)) * STG_SZ;
                const size_t kb = (size_t)ks2 * 64;
                const char* pa = aBase + kb;
                const char* pb = bBase + (size_t)nt2 * NT_B + kb;
                CP16(dA + soff,                pa);
                CP16(dA + soff +  64 * PITCHB, pa + R64);
                CP16(dA + soff + 128 * PITCHB, pa + 2 * R64);
                CP16(dA + soff + 192 * PITCHB, pa + 3 * R64);
                CP16(dB + soff,                pb);
                CP16(dB + soff +  64 * PITCHB, pb + R64);
                CP_COMMIT();
            }

#pragma unroll
            for (int s = 0; s < 2; s++) {   // two k16 steps
                uint32_t Ah[4][4];
#pragma unroll
                for (int i = 0; i < 4; i++)
                    LDSM4(Ah[i], sb + sbase + aOff + i * 1280 + s * 32);
#pragma unroll
                for (int g = 0; g < 4; g++) {
                    uint32_t Bh[4];
                    LDSM4(Bh, sb + sbase + bOff + g * 1280 + s * 32);
#pragma unroll
                    for (int i = 0; i < 4; i++) {
                        MMAF16(acc[i][2 * g],     Ah[i], Bh[0], Bh[1]);
                        MMAF16(acc[i][2 * g + 1], Ah[i], Bh[2], Bh[3]);
                    }
                }
            }
        }

        // pass epilogue: tanh + dot(v) into row partials (out of the hot loop)
#pragma unroll
        for (int j = 0; j < 8; j++) {
            const int n = nt * BNT + WN + j * 8 + (l & 3) * 2;
            const float2 pq2 = *(const float2*)(smem + OFF_PQ + n * 4);
            const float2 v2  = *(const float2*)(smem + OFF_V  + n * 4);
#pragma unroll
            for (int i = 0; i < 4; i++) {
#pragma unroll
                for (int h = 0; h < 2; h++) {
                    p8[i * 2 + h] += tanhf(acc[i][j][h * 2]     + pq2.x) * v2.x
                                   + tanhf(acc[i][j][h * 2 + 1] + pq2.y) * v2.y;
                }
            }
        }
    }

    // quad reduce (columns within quad), then cross-warpN reduce via smem
#pragma unroll
    for (int pi = 0; pi < 8; pi++) {
        float x = p8[pi];
        x += __shfl_xor_sync(0xffffffffu, x, 1);
        x += __shfl_xor_sync(0xffffffffu, x, 2);
        p8[pi] = x;
    }
    float* red = (float*)(smem + OFF_RED);
    if ((l & 3) == 0) {
#pragma unroll
        for (int pi = 0; pi < 8; pi++) {
            const int row = WM + (pi >> 1) * 16 + (pi & 1) * 8 + (l >> 2);
            red[(wid & 1) * 256 + row] = p8[pi];
        }
    }
    __syncthreads();
    if (m0 + t < cnt) {
        const float sum = red[t] + red[256 + t];
        g_react[b * NS + g_sidx[b * NS + m0 + t]] = sum;
    }
}

// ---------------------------------------------------------------------------
// Kernel 3: masked softmax over S per batch; writes scores into out.
// ---------------------------------------------------------------------------
__global__ void softmax_kernel(const int* __restrict__ weights,
                               float* __restrict__ out)
{
    const int b = blockIdx.x;
    const int t = threadIdx.x;
    __shared__ float sm[256];

    float vals[NS / 256];
    float mx = -INFINITY;
#pragma unroll
    for (int r = 0; r < NS / 256; r++) {
        const int s = t + r * 256;
        const float x = (weights[b * NS + s] == 0) ? -INFINITY
                                                   : g_react[b * NS + s];
        vals[r] = x;
        mx = fmaxf(mx, x);
    }
    sm[t] = mx; __syncthreads();
    for (int off = 128; off > 0; off >>= 1) {
        if (t < off) sm[t] = fmaxf(sm[t], sm[t + off]);
        __syncthreads();
    }
    mx = sm[0];
    __syncthreads();

    float sum = 0.f;
#pragma unroll
    for (int r = 0; r < NS / 256; r++) {
        vals[r] = expf(vals[r] - mx);
        sum += vals[r];
    }
    sm[t] = sum; __syncthreads();
    for (int off = 128; off > 0; off >>= 1) {
        if (t < off) sm[t] += sm[t + off];
        __syncthreads();
    }
    const float inv = 1.f / sm[0];

    float* scores = out + NB * NI + (size_t)b * NS;
#pragma unroll
    for (int r = 0; r < NS / 256; r++)
        scores[t + r * 256] = vals[r] * inv;
}

// ---------------------------------------------------------------------------
// Kernel 4a: blended partials over compacted fp16 rows (scores pre-gathered)
// ---------------------------------------------------------------------------
__global__ void blend_partial_kernel(const float* __restrict__ out)
{
    __shared__ float ws[NS / NCH];
    const int b  = blockIdx.x;
    const int ch = blockIdx.y;
    const int j0 = ch * (NS / NCH);
    const int cnt = g_cnt[b];
    const float* __restrict__ scores = out + NB * NI + (size_t)b * NS;

    if (threadIdx.x < NS / NCH) {
        const int j = j0 + threadIdx.x;
        ws[threadIdx.x] = (j < cnt) ? scores[g_sidx[b * NS + j]] : 0.f;
    }
    __syncthreads();

    const int i = threadIdx.x * 4;
    const __half* __restrict__ base = g_it16 + ((size_t)b * NS + j0) * NI + i;
    float4 acc = make_float4(0.f, 0.f, 0.f, 0.f);
    for (int jj = 0; jj < NS / NCH; jj++) {
        const float w = ws[jj];
        if (w != 0.f) {
            const uint2 hv = *(const uint2*)(base + (size_t)jj * NI);
            const __half2 h0 = *reinterpret_cast<const __half2*>(&hv.x);
            const __half2 h1 = *reinterpret_cast<const __half2*>(&hv.y);
            const float2 f0 = __half22float2(h0);
            const float2 f1 = __half22float2(h1);
            acc.x = fmaf(w, f0.x, acc.x);
            acc.y = fmaf(w, f0.y, acc.y);
            acc.z = fmaf(w, f1.x, acc.z);
            acc.w = fmaf(w, f1.y, acc.w);
        }
    }
    *(float4*)(g_bpart + (size_t)(b * NCH + ch) * NI + i) = acc;
}

// ---------------------------------------------------------------------------
// Kernel 4b: reduce partials -> blended
// ---------------------------------------------------------------------------
__global__ void blend_reduce_kernel(float* __restrict__ out)
{
    const int b = blockIdx.x;
    const int i = threadIdx.x * 4;
    float4 acc = make_float4(0.f, 0.f, 0.f, 0.f);
    for (int c = 0; c < NCH; c++) {
        const float4 x = *(const float4*)(g_bpart + (size_t)(b * NCH + c) * NI + i);
        acc.x += x.x; acc.y += x.y; acc.z += x.z; acc.w += x.w;
    }
    *(float4*)(out + (size_t)b * NI + i) = acc;
}

// ---------------------------------------------------------------------------
extern "C" void kernel_launch(void* const* d_in, const int* in_sizes, int n_in,
                              void* d_out, int out_size)
{
    const float* queries = (const float*)d_in[0];
    const float* items   = (const float*)d_in[1];
    const int*   weights = (const int*)  d_in[2];
    const float* W       = (const float*)d_in[3];
    const float* U       = (const float*)d_in[4];
    const float* v       = (const float*)d_in[5];
    float* out = (float*)d_out;   // [B*I blended | B*S scores]

    static int attr_set = 0;
    if (!attr_set) {
        cudaFuncSetAttribute(react_kernel,
                             cudaFuncAttributeMaxDynamicSharedMemorySize, SM_TOTAL);
        attr_set = 1;
    }

    compact_kernel<<<NB, 32>>>(weights);
    pq_kernel<<<dim3(NB, NA / 256), 256>>>(queries, W);
    transpose_kernel<<<dim3(NA / 32, NI / 32), dim3(32, 8)>>>(U);
    convert_items_kernel<<<dim3(NS / 4, NB), 256>>>(items);
    react_kernel<<<dim3(NS / BMT, NB), 256, SM_TOTAL>>>(v);
    softmax_kernel<<<NB, 256>>>(weights, out);
    blend_partial_kernel<<<dim3(NB, NCH), 256>>>(out);
    blend_reduce_kernel<<<NB, 256>>>(out);
}

// round 7
// speedup vs baseline: 10.2137x; 1.0389x over previous
#include <cuda_runtime.h>
#include <cuda_fp16.h>
#include <math.h>
#include <stdint.h>

#define NB 32
#define NS 2048
#define NQ 1024
#define NI 1024
#define NA 1024
#define NCH 16      // s-chunks; 2 partial slots per chunk (thread parity)

// ---- react tiling ----
#define BMT 256                 // CTA m tile (1-wave grid)
#define BNT 128                 // CTA n tile (8 passes)
#define BK  32                  // k per stage
#define NSTG 4                  // cp.async pipeline depth
#define PITCHB 80               // smem row pitch bytes (64B data; conflict-free ldmatrix)
#define STG_A 0
#define STG_B (256 * PITCHB)            // 20480
#define STG_SZ (STG_B + 128 * PITCHB)   // 30720
#define OFF_PQ (NSTG * STG_SZ)          // 122880
#define OFF_V  (OFF_PQ + 4096)
#define OFF_RED (OFF_V + 4096)
#define SM_TOTAL (OFF_RED + 2048)       // 133120 bytes

// scratch (device globals: allocation-free per harness rules)
__device__ float g_pq[NB * NA];
__device__ float g_react[NB * NS];
__device__ float g_bpart[NB * 2 * NCH * NI];
__device__ int   g_sidx[NB * NS];
__device__ int   g_cnt[NB];
__device__ __half g_ut16[NA * NI];                // [n][k] fp16
__device__ __half g_it16[(size_t)NB * NS * NI];   // [b][j][k] fp16, gather-compacted

// ---------------------------------------------------------------------------
// PTX helpers (baseline ISA: mma.sync f16, ldmatrix, cp.async — all sm_80)
// ---------------------------------------------------------------------------
__device__ __forceinline__ uint32_t smem_u32(const void* p) {
    uint32_t a;
    asm("{ .reg .u64 t; cvta.to.shared.u64 t, %1; cvt.u32.u64 %0, t; }"
        : "=r"(a) : "l"(p));
    return a;
}

#define LDSM4(r, addr) \
    asm volatile("ldmatrix.sync.aligned.m8n8.x4.shared.b16 {%0,%1,%2,%3}, [%4];" \
        : "=r"((r)[0]), "=r"((r)[1]), "=r"((r)[2]), "=r"((r)[3]) : "r"(addr))

#define MMAF16(d, a, b0v, b1v) \
    asm volatile("mma.sync.aligned.m16n8k16.row.col.f32.f16.f16.f32 " \
        "{%0,%1,%2,%3}, {%4,%5,%6,%7}, {%8,%9}, {%0,%1,%2,%3};" \
        : "+f"((d)[0]), "+f"((d)[1]), "+f"((d)[2]), "+f"((d)[3]) \
        : "r"((a)[0]), "r"((a)[1]), "r"((a)[2]), "r"((a)[3]), \
          "r"(b0v), "r"(b1v))

#define CP16(dst, src) \
    asm volatile("cp.async.cg.shared.global [%0], [%1], 16;" \
        :: "r"(dst), "l"(src) : "memory")
#define CP_COMMIT() asm volatile("cp.async.commit_group;" ::: "memory")
#define CP_WAIT2()  asm volatile("cp.async.wait_group 2;" ::: "memory")

__device__ __forceinline__ float tanha(float x) {   // MUFU.TANH
    float y;
    asm("tanh.approx.f32 %0, %1;" : "=f"(y) : "f"(x));
    return y;
}

// ---------------------------------------------------------------------------
// Kernel 0: per-batch compaction of active s-indices
// ---------------------------------------------------------------------------
__global__ void compact_kernel(const int* __restrict__ weights)
{
    const int b = blockIdx.x;
    const int lane = threadIdx.x;
    int base = 0;
    for (int c = 0; c < NS / 32; c++) {
        const int s = c * 32 + lane;
        const int active = (weights[b * NS + s] != 0);
        const unsigned m = __ballot_sync(0xffffffffu, active);
        const int pre = __popc(m & ((1u << lane) - 1u));
        if (active) g_sidx[b * NS + base + pre] = s;
        base += __popc(m);
    }
    if (lane == 0) g_cnt[b] = base;
}

// ---------------------------------------------------------------------------
// Kernel 1: pq[b,a] = queries[b] @ W
// ---------------------------------------------------------------------------
__global__ void pq_kernel(const float* __restrict__ queries,
                          const float* __restrict__ W)
{
    const int b = blockIdx.x;
    const int a = blockIdx.y * 256 + threadIdx.x;
    __shared__ float qs[NQ];
    for (int i = threadIdx.x; i < NQ; i += 256) qs[i] = queries[b * NQ + i];
    __syncthreads();
    float acc = 0.f;
#pragma unroll 8
    for (int q = 0; q < NQ; q++) acc = fmaf(qs[q], W[(size_t)q * NA + a], acc);
    g_pq[b * NA + a] = acc;
}

// ---------------------------------------------------------------------------
// Kernel 1b: transpose U -> Ut fp16 [n][k]
// ---------------------------------------------------------------------------
__global__ void transpose_kernel(const float* __restrict__ U)
{
    __shared__ float tile[32][33];
    const int n0 = blockIdx.x * 32, k0 = blockIdx.y * 32;
    const int tx = threadIdx.x, ty = threadIdx.y;  // 32 x 8
#pragma unroll
    for (int i = 0; i < 32; i += 8)
        tile[ty + i][tx] = U[(size_t)(k0 + ty + i) * NA + n0 + tx];
    __syncthreads();
#pragma unroll
    for (int i = 0; i < 32; i += 8) {
        const int n = n0 + ty + i, k = k0 + tx;
        g_ut16[(size_t)n * NI + k] = __float2half(tile[tx][ty + i]);
    }
}

// ---------------------------------------------------------------------------
// Kernel 1c: gather-compact items -> fp16 (active rows; 16 elems/thread MLP)
// ---------------------------------------------------------------------------
__global__ void convert_items_kernel(const float* __restrict__ items)
{
    const int b = blockIdx.y;
    const int j = blockIdx.x * 4 + (threadIdx.x >> 6);
    if (j >= g_cnt[b]) return;
    const int s = g_sidx[b * NS + j];
    const int off = (threadIdx.x & 63) * 16;
    const float* src = items + ((size_t)b * NS + s) * NI + off;
    const float4 f0 = *(const float4*)(src);
    const float4 f1 = *(const float4*)(src + 4);
    const float4 f2 = *(const float4*)(src + 8);
    const float4 f3 = *(const float4*)(src + 12);
    __half2 h0 = __floats2half2_rn(f0.x, f0.y);
    __half2 h1 = __floats2half2_rn(f0.z, f0.w);
    __half2 h2 = __floats2half2_rn(f1.x, f1.y);
    __half2 h3 = __floats2half2_rn(f1.z, f1.w);
    __half2 h4 = __floats2half2_rn(f2.x, f2.y);
    __half2 h5 = __floats2half2_rn(f2.z, f2.w);
    __half2 h6 = __floats2half2_rn(f3.x, f3.y);
    __half2 h7 = __floats2half2_rn(f3.z, f3.w);
    uint4 o0, o1;
    o0.x = *reinterpret_cast<uint32_t*>(&h0);
    o0.y = *reinterpret_cast<uint32_t*>(&h1);
    o0.z = *reinterpret_cast<uint32_t*>(&h2);
    o0.w = *reinterpret_cast<uint32_t*>(&h3);
    o1.x = *reinterpret_cast<uint32_t*>(&h4);
    o1.y = *reinterpret_cast<uint32_t*>(&h5);
    o1.z = *reinterpret_cast<uint32_t*>(&h6);
    o1.w = *reinterpret_cast<uint32_t*>(&h7);
    __half* dst = g_it16 + ((size_t)b * NS + j) * NI + off;
    *(uint4*)(dst) = o0;
    *(uint4*)(dst + 8) = o1;
}

// ---------------------------------------------------------------------------
// Kernel 2 (dominant): single-stream fp16 GEMM on mma.sync + fused epilogue.
// CTA: 256 compacted m-rows x 128 n per pass (8 passes), 8 warps 64x64 tiles,
// 4-stage cp.async pipeline, BK=32. Epilogue uses MUFU tanh.approx.
// ---------------------------------------------------------------------------
__global__ void __launch_bounds__(256, 1)
react_kernel(const float* __restrict__ v)
{
    extern __shared__ char smem[];
    const int b   = blockIdx.y;
    const int cnt = g_cnt[b];
    const int m0  = blockIdx.x * BMT;
    if (m0 >= cnt) return;

    const uint32_t sb = smem_u32(smem);
    const int t   = threadIdx.x;
    const int wid = t >> 5;
    const int l   = t & 31;
    const int WM  = (wid >> 1) * 64;
    const int WN  = (wid & 1) * 64;

    // stage pq + v (full 1024 each)
    {
        const float* __restrict__ pqg = g_pq + b * NA;
        ((float4*)(smem + OFF_PQ))[t] = ((const float4*)pqg)[t];
        ((float4*)(smem + OFF_V))[t]  = ((const float4*)v)[t];
    }

    // loader mapping: 6 cp.async(16B) per stage per thread
    const int rA = t >> 2;                // 0..63
    const uint32_t q16 = (t & 3) * 16;
    const char* aBase = (const char*)(g_it16 + ((size_t)b * NS + m0 + rA) * NI) + q16;
    const char* bBase = (const char*)(g_ut16 + (size_t)rA * NI) + q16;
    const uint32_t dA = sb + STG_A + rA * PITCHB + q16;
    const uint32_t dB = sb + STG_B + rA * PITCHB + q16;
    const size_t R64  = (size_t)64 * NI * 2;    // 64 rows in bytes
    const size_t NT_B = (size_t)128 * NI * 2;   // one 128-n B panel in bytes

    // ldmatrix lane offsets (within stage)
    const uint32_t aOff = STG_A + (WM + (l & 15)) * PITCHB + (l >> 4) * 16;
    const uint32_t bOff = STG_B + (WN + (l & 7) + ((l >> 4) & 1) * 8) * PITCHB
                          + ((l >> 3) & 1) * 16;

    float acc[4][8][4];
    float p8[8];
#pragma unroll
    for (int i = 0; i < 8; i++) p8[i] = 0.f;

    // pipeline prologue: stages 0..2 (all nt=0)
#pragma unroll
    for (int p = 0; p < NSTG - 1; p++) {
        const uint32_t soff = p * STG_SZ;
        const size_t kb = (size_t)p * 64;
        const char* pa = aBase + kb;
        const char* pb = bBase + kb;
        CP16(dA + soff,                pa);
        CP16(dA + soff +  64 * PITCHB, pa + R64);
        CP16(dA + soff + 128 * PITCHB, pa + 2 * R64);
        CP16(dA + soff + 192 * PITCHB, pa + 3 * R64);
        CP16(dB + soff,                pb);
        CP16(dB + soff +  64 * PITCHB, pb + R64);
        CP_COMMIT();
    }

#pragma unroll 1
    for (int nt = 0; nt < NA / BNT; nt++) {
#pragma unroll
        for (int i = 0; i < 4; i++)
#pragma unroll
            for (int j = 0; j < 8; j++)
#pragma unroll
                for (int c = 0; c < 4; c++) acc[i][j][c] = 0.f;

#pragma unroll 4
        for (int ks = 0; ks < 32; ks++) {
            const int sg = nt * 32 + ks;
            const uint32_t sbase = (uint32_t)(sg & (NSTG - 1)) * STG_SZ;

            CP_WAIT2();
            __syncthreads();

            // issue stage sg+3
            const int s2 = sg + NSTG - 1;
            if (s2 < 256) {
                const int ks2 = s2 & 31, nt2 = s2 >> 5;
                const uint32_t soff = (uint32_t)(s2 & (NSTG - 1)) * STG_SZ;
                const size_t kb = (size_t)ks2 * 64;
                const char* pa = aBase + kb;
                const char* pb = bBase + (size_t)nt2 * NT_B + kb;
                CP16(dA + soff,                pa);
                CP16(dA + soff +  64 * PITCHB, pa + R64);
                CP16(dA + soff + 128 * PITCHB, pa + 2 * R64);
                CP16(dA + soff + 192 * PITCHB, pa + 3 * R64);
                CP16(dB + soff,                pb);
                CP16(dB + soff +  64 * PITCHB, pb + R64);
                CP_COMMIT();
            }

#pragma unroll
            for (int s = 0; s < 2; s++) {   // two k16 steps
                uint32_t Ah[4][4];
#pragma unroll
                for (int i = 0; i < 4; i++)
                    LDSM4(Ah[i], sb + sbase + aOff + i * 1280 + s * 32);
#pragma unroll
                for (int g = 0; g < 4; g++) {
                    uint32_t Bh[4];
                    LDSM4(Bh, sb + sbase + bOff + g * 1280 + s * 32);
#pragma unroll
                    for (int i = 0; i < 4; i++) {
                        MMAF16(acc[i][2 * g],     Ah[i], Bh[0], Bh[1]);
                        MMAF16(acc[i][2 * g + 1], Ah[i], Bh[2], Bh[3]);
                    }
                }
            }
        }

        // pass epilogue: MUFU tanh + dot(v) into row partials
#pragma unroll
        for (int j = 0; j < 8; j++) {
            const int n = nt * BNT + WN + j * 8 + (l & 3) * 2;
            const float2 pq2 = *(const float2*)(smem + OFF_PQ + n * 4);
            const float2 v2  = *(const float2*)(smem + OFF_V  + n * 4);
#pragma unroll
            for (int i = 0; i < 4; i++) {
#pragma unroll
                for (int h = 0; h < 2; h++) {
                    p8[i * 2 + h] += tanha(acc[i][j][h * 2]     + pq2.x) * v2.x
                                   + tanha(acc[i][j][h * 2 + 1] + pq2.y) * v2.y;
                }
            }
        }
    }

    // quad reduce (columns within quad), then cross-warpN reduce via smem
#pragma unroll
    for (int pi = 0; pi < 8; pi++) {
        float x = p8[pi];
        x += __shfl_xor_sync(0xffffffffu, x, 1);
        x += __shfl_xor_sync(0xffffffffu, x, 2);
        p8[pi] = x;
    }
    float* red = (float*)(smem + OFF_RED);
    if ((l & 3) == 0) {
#pragma unroll
        for (int pi = 0; pi < 8; pi++) {
            const int row = WM + (pi >> 1) * 16 + (pi & 1) * 8 + (l >> 2);
            red[(wid & 1) * 256 + row] = p8[pi];
        }
    }
    __syncthreads();
    if (m0 + t < cnt) {
        const float sum = red[t] + red[256 + t];
        g_react[b * NS + g_sidx[b * NS + m0 + t]] = sum;
    }
}

// ---------------------------------------------------------------------------
// Kernel 3: masked softmax over S per batch; writes scores into out.
// ---------------------------------------------------------------------------
__global__ void softmax_kernel(const int* __restrict__ weights,
                               float* __restrict__ out)
{
    const int b = blockIdx.x;
    const int t = threadIdx.x;
    __shared__ float sm[256];

    float vals[NS / 256];
    float mx = -INFINITY;
#pragma unroll
    for (int r = 0; r < NS / 256; r++) {
        const int s = t + r * 256;
        const float x = (weights[b * NS + s] == 0) ? -INFINITY
                                                   : g_react[b * NS + s];
        vals[r] = x;
        mx = fmaxf(mx, x);
    }
    sm[t] = mx; __syncthreads();
    for (int off = 128; off > 0; off >>= 1) {
        if (t < off) sm[t] = fmaxf(sm[t], sm[t + off]);
        __syncthreads();
    }
    mx = sm[0];
    __syncthreads();

    float sum = 0.f;
#pragma unroll
    for (int r = 0; r < NS / 256; r++) {
        vals[r] = expf(vals[r] - mx);
        sum += vals[r];
    }
    sm[t] = sum; __syncthreads();
    for (int off = 128; off > 0; off >>= 1) {
        if (t < off) sm[t] += sm[t + off];
        __syncthreads();
    }
    const float inv = 1.f / sm[0];

    float* scores = out + NB * NI + (size_t)b * NS;
#pragma unroll
    for (int r = 0; r < NS / 256; r++)
        scores[t + r * 256] = vals[r] * inv;
}

// ---------------------------------------------------------------------------
// Kernel 4a: blended partials (fp16 rows, LDG.128, 2 parity slots per chunk)
// ---------------------------------------------------------------------------
__global__ void blend_partial_kernel(const float* __restrict__ out)
{
    __shared__ float ws[NS / NCH];
    const int b   = blockIdx.x;
    const int ch  = blockIdx.y;
    const int j0  = ch * (NS / NCH);
    const int cnt = g_cnt[b];
    const float* __restrict__ scores = out + NB * NI + (size_t)b * NS;

    if (threadIdx.x < NS / NCH) {
        const int j = j0 + threadIdx.x;
        ws[threadIdx.x] = (j < cnt) ? scores[g_sidx[b * NS + j]] : 0.f;
    }
    __syncthreads();

    const int half = threadIdx.x >> 7;         // s parity
    const int col  = (threadIdx.x & 127) * 8;  // 8 halfs = 16B
    const __half* __restrict__ base = g_it16 + ((size_t)b * NS + j0) * NI + col;

    float a0 = 0.f, a1 = 0.f, a2 = 0.f, a3 = 0.f;
    float a4 = 0.f, a5 = 0.f, a6 = 0.f, a7 = 0.f;
    for (int jj = half; jj < NS / NCH; jj += 2) {
        const float w = ws[jj];
        if (w != 0.f) {
            const uint4 hv = *(const uint4*)(base + (size_t)jj * NI);
            const float2 f0 = __half22float2(*reinterpret_cast<const __half2*>(&hv.x));
            const float2 f1 = __half22float2(*reinterpret_cast<const __half2*>(&hv.y));
            const float2 f2 = __half22float2(*reinterpret_cast<const __half2*>(&hv.z));
            const float2 f3 = __half22float2(*reinterpret_cast<const __half2*>(&hv.w));
            a0 = fmaf(w, f0.x, a0); a1 = fmaf(w, f0.y, a1);
            a2 = fmaf(w, f1.x, a2); a3 = fmaf(w, f1.y, a3);
            a4 = fmaf(w, f2.x, a4); a5 = fmaf(w, f2.y, a5);
            a6 = fmaf(w, f3.x, a6); a7 = fmaf(w, f3.y, a7);
        }
    }
    float* dst = g_bpart + (size_t)((b * NCH + ch) * 2 + half) * NI + col;
    *(float4*)(dst)     = make_float4(a0, a1, a2, a3);
    *(float4*)(dst + 4) = make_float4(a4, a5, a6, a7);
}

// ---------------------------------------------------------------------------
// Kernel 4b: reduce partials -> blended
// ---------------------------------------------------------------------------
__global__ void blend_reduce_kernel(float* __restrict__ out)
{
    const int b = blockIdx.x;
    const int i = threadIdx.x * 4;
    float4 acc = make_float4(0.f, 0.f, 0.f, 0.f);
    for (int c = 0; c < 2 * NCH; c++) {
        const float4 x = *(const float4*)(g_bpart + (size_t)(b * 2 * NCH + c) * NI + i);
        acc.x += x.x; acc.y += x.y; acc.z += x.z; acc.w += x.w;
    }
    *(float4*)(out + (size_t)b * NI + i) = acc;
}

// ---------------------------------------------------------------------------
extern "C" void kernel_launch(void* const* d_in, const int* in_sizes, int n_in,
                              void* d_out, int out_size)
{
    const float* queries = (const float*)d_in[0];
    const float* items   = (const float*)d_in[1];
    const int*   weights = (const int*)  d_in[2];
    const float* W       = (const float*)d_in[3];
    const float* U       = (const float*)d_in[4];
    const float* v       = (const float*)d_in[5];
    float* out = (float*)d_out;   // [B*I blended | B*S scores]

    static cudaStream_t s1 = nullptr;
    static cudaEvent_t eFork = nullptr, eJoin = nullptr;
    if (s1 == nullptr) {
        cudaFuncSetAttribute(react_kernel,
                             cudaFuncAttributeMaxDynamicSharedMemorySize, SM_TOTAL);
        cudaStreamCreateWithFlags(&s1, cudaStreamNonBlocking);
        cudaEventCreateWithFlags(&eFork, cudaEventDisableTiming);
        cudaEventCreateWithFlags(&eJoin, cudaEventDisableTiming);
    }

    // fork: pq + transpose on s1, compact -> convert on main stream
    cudaEventRecord(eFork, 0);
    cudaStreamWaitEvent(s1, eFork, 0);
    pq_kernel<<<dim3(NB, NA / 256), 256, 0, s1>>>(queries, W);
    transpose_kernel<<<dim3(NA / 32, NI / 32), dim3(32, 8), 0, s1>>>(U);
    cudaEventRecord(eJoin, s1);

    compact_kernel<<<NB, 32>>>(weights);
    convert_items_kernel<<<dim3(NS / 4, NB), 256>>>(items);

    // join, then the dependent chain
    cudaStreamWaitEvent(0, eJoin, 0);
    react_kernel<<<dim3(NS / BMT, NB), 256, SM_TOTAL>>>(v);
    softmax_kernel<<<NB, 256>>>(weights, out);
    blend_partial_kernel<<<dim3(NB, NCH), 256>>>(out);
    blend_reduce_kernel<<<NB, 256>>>(out);
}

// round 9
// speedup vs baseline: 10.3854x; 1.0168x over previous
#include <cuda_runtime.h>
#include <cuda_fp16.h>
#include <math.h>
#include <stdint.h>

#define NB 32
#define NS 2048
#define NQ 1024
#define NI 1024
#define NA 1024
#define NCH 16      // s-chunks; 2 partial slots per chunk (thread parity)
#define NCHK 4      // batch chunks (8 batches each) for M-flattening

// ---- react tiling ----
#define BMT 256                 // CTA m tile
#define BNT 128                 // CTA n tile (8 passes)
#define BK  32                  // k per stage
#define NSTG 4                  // cp.async pipeline depth
#define PITCHB 80               // smem row pitch bytes (64B data; conflict-free ldmatrix)
#define STG_A 0
#define STG_B (256 * PITCHB)            // 20480
#define STG_SZ (STG_B + 128 * PITCHB)   // 30720
#define OFF_PQ (NSTG * STG_SZ)          // 122880 (2 x 4096: pq rows b0,b1)
#define OFF_V  (OFF_PQ + 8192)
#define OFF_RED (OFF_V + 4096)
#define SM_TOTAL (OFF_RED + 2048)       // 137216 bytes

// scratch (device globals: allocation-free per harness rules)
__device__ float g_pq[NB * NA];
__device__ float g_react[NB * NS];
__device__ float g_bpart[NB * 2 * NCH * NI];
__device__ int   g_sidx[NB * NS];
__device__ int   g_cnt[NB];
__device__ int   g_woff[NB];         // flat packed row of batch b's first row
__device__ int   g_loffc[NCHK * 9];  // per-chunk local prefix (incl. total)
__device__ __half g_ut16[NA * NI];                        // [n][k] fp16
__device__ __half g_it16[((size_t)NB * NS + 256) * NI];   // flat packed rows (+pad)

// ---------------------------------------------------------------------------
// PTX helpers (baseline ISA: mma.sync f16, ldmatrix, cp.async — all sm_80)
// ---------------------------------------------------------------------------
__device__ __forceinline__ uint32_t smem_u32(const void* p) {
    uint32_t a;
    asm("{ .reg .u64 t; cvta.to.shared.u64 t, %1; cvt.u32.u64 %0, t; }"
        : "=r"(a) : "l"(p));
    return a;
}

#define LDSM4(r, addr) \
    asm volatile("ldmatrix.sync.aligned.m8n8.x4.shared.b16 {%0,%1,%2,%3}, [%4];" \
        : "=r"((r)[0]), "=r"((r)[1]), "=r"((r)[2]), "=r"((r)[3]) : "r"(addr))

#define MMAF16(d, a, b0v, b1v) \
    asm volatile("mma.sync.aligned.m16n8k16.row.col.f32.f16.f16.f32 " \
        "{%0,%1,%2,%3}, {%4,%5,%6,%7}, {%8,%9}, {%0,%1,%2,%3};" \
        : "+f"((d)[0]), "+f"((d)[1]), "+f"((d)[2]), "+f"((d)[3]) \
        : "r"((a)[0]), "r"((a)[1]), "r"((a)[2]), "r"((a)[3]), \
          "r"(b0v), "r"(b1v))

#define CP16(dst, src) \
    asm volatile("cp.async.cg.shared.global [%0], [%1], 16;" \
        :: "r"(dst), "l"(src) : "memory")
#define CP_COMMIT() asm volatile("cp.async.commit_group;" ::: "memory")
#define CP_WAIT2()  asm volatile("cp.async.wait_group 2;" ::: "memory")

__device__ __forceinline__ float tanha(float x) {   // MUFU.TANH
    float y;
    asm("tanh.approx.f32 %0, %1;" : "=f"(y) : "f"(x));
    return y;
}

// ---------------------------------------------------------------------------
// Kernel 0: per-batch compaction of active s-indices
// ---------------------------------------------------------------------------
__global__ void compact_kernel(const int* __restrict__ weights)
{
    const int b = blockIdx.x;
    const int lane = threadIdx.x;
    int base = 0;
    for (int c = 0; c < NS / 32; c++) {
        const int s = c * 32 + lane;
        const int active = (weights[b * NS + s] != 0);
        const unsigned m = __ballot_sync(0xffffffffu, active);
        const int pre = __popc(m & ((1u << lane) - 1u));
        if (active) g_sidx[b * NS + base + pre] = s;
        base += __popc(m);
    }
    if (lane == 0) g_cnt[b] = base;
}

// ---------------------------------------------------------------------------
// Kernel 0b: per-chunk prefix sums of cnt (trivial size)
// ---------------------------------------------------------------------------
__global__ void prefix_kernel()
{
    if (threadIdx.x != 0) return;
    for (int c = 0; c < NCHK; c++) {
        int acc = 0;
        for (int i = 0; i < 8; i++) {
            const int b = c * 8 + i;
            g_woff[b] = c * 8 * NS + acc;
            g_loffc[c * 9 + i] = acc;
            acc += g_cnt[b];
        }
        g_loffc[c * 9 + 8] = acc;
    }
}

// ---------------------------------------------------------------------------
// Kernel 1: pq[b,a] = queries[b] @ W
// ---------------------------------------------------------------------------
__global__ void pq_kernel(const float* __restrict__ queries,
                          const float* __restrict__ W)
{
    const int b = blockIdx.x;
    const int a = blockIdx.y * 256 + threadIdx.x;
    __shared__ float qs[NQ];
    for (int i = threadIdx.x; i < NQ; i += 256) qs[i] = queries[b * NQ + i];
    __syncthreads();
    float acc = 0.f;
#pragma unroll 8
    for (int q = 0; q < NQ; q++) acc = fmaf(qs[q], W[(size_t)q * NA + a], acc);
    g_pq[b * NA + a] = acc;
}

// ---------------------------------------------------------------------------
// Kernel 1b: transpose U -> Ut fp16 [n][k]
// ---------------------------------------------------------------------------
__global__ void transpose_kernel(const float* __restrict__ U)
{
    __shared__ float tile[32][33];
    const int n0 = blockIdx.x * 32, k0 = blockIdx.y * 32;
    const int tx = threadIdx.x, ty = threadIdx.y;  // 32 x 8
#pragma unroll
    for (int i = 0; i < 32; i += 8)
        tile[ty + i][tx] = U[(size_t)(k0 + ty + i) * NA + n0 + tx];
    __syncthreads();
#pragma unroll
    for (int i = 0; i < 32; i += 8) {
        const int n = n0 + ty + i, k = k0 + tx;
        g_ut16[(size_t)n * NI + k] = __float2half(tile[tx][ty + i]);
    }
}

// ---------------------------------------------------------------------------
// Kernel 1c: gather-compact items -> fp16 at flat packed rows
// ---------------------------------------------------------------------------
__global__ void convert_items_kernel(const float* __restrict__ items)
{
    const int b = blockIdx.y;
    const int j = blockIdx.x * 4 + (threadIdx.x >> 6);
    if (j >= g_cnt[b]) return;
    const int s = g_sidx[b * NS + j];
    const int off = (threadIdx.x & 63) * 16;
    const float* src = items + ((size_t)b * NS + s) * NI + off;
    const float4 f0 = *(const float4*)(src);
    const float4 f1 = *(const float4*)(src + 4);
    const float4 f2 = *(const float4*)(src + 8);
    const float4 f3 = *(const float4*)(src + 12);
    __half2 h0 = __floats2half2_rn(f0.x, f0.y);
    __half2 h1 = __floats2half2_rn(f0.z, f0.w);
    __half2 h2 = __floats2half2_rn(f1.x, f1.y);
    __half2 h3 = __floats2half2_rn(f1.z, f1.w);
    __half2 h4 = __floats2half2_rn(f2.x, f2.y);
    __half2 h5 = __floats2half2_rn(f2.z, f2.w);
    __half2 h6 = __floats2half2_rn(f3.x, f3.y);
    __half2 h7 = __floats2half2_rn(f3.z, f3.w);
    uint4 o0, o1;
    o0.x = *reinterpret_cast<uint32_t*>(&h0);
    o0.y = *reinterpret_cast<uint32_t*>(&h1);
    o0.z = *reinterpret_cast<uint32_t*>(&h2);
    o0.w = *reinterpret_cast<uint32_t*>(&h3);
    o1.x = *reinterpret_cast<uint32_t*>(&h4);
    o1.y = *reinterpret_cast<uint32_t*>(&h5);
    o1.z = *reinterpret_cast<uint32_t*>(&h6);
    o1.w = *reinterpret_cast<uint32_t*>(&h7);
    __half* dst = g_it16 + ((size_t)(g_woff[b] + j)) * NI + off;
    *(uint4*)(dst) = o0;
    *(uint4*)(dst + 8) = o1;
}

// ---------------------------------------------------------------------------
// Kernel 2 (dominant): fp16 GEMM on mma.sync, M flattened across each chunk's
// 8 batches (packed rows -> ~1.5% pad vs 12%). chunk = blockIdx.y; surplus
// tiles early-exit. A tile spans <=2 batches; epilogue selects between two
// staged pq rows per accumulator row.
// ---------------------------------------------------------------------------
__global__ void __launch_bounds__(256, 1)
react_kernel(const float* __restrict__ v)
{
    extern __shared__ char smem[];
    const int chunk = blockIdx.y;
    int loff[9];
#pragma unroll
    for (int i = 0; i < 9; i++) loff[i] = g_loffc[chunk * 9 + i];
    const int chunkcnt = loff[8];
    const int m0 = blockIdx.x * BMT;
    if (m0 >= chunkcnt) return;

    // batches spanned by this tile (<=2 for realistic cnt)
    int b0 = 0, b1 = 0;
    const int rlast = min(m0 + BMT - 1, chunkcnt - 1);
#pragma unroll
    for (int i = 1; i < 8; i++) {
        if (loff[i] <= m0) b0 = i;
        if (loff[i] <= rlast) b1 = i;
    }
    const int bound = (b1 > b0) ? loff[b0 + 1] : (chunkcnt + BMT);

    const uint32_t sb = smem_u32(smem);
    const int t   = threadIdx.x;
    const int wid = t >> 5;
    const int l   = t & 31;
    const int WM  = (wid >> 1) * 64;
    const int WN  = (wid & 1) * 64;

    // stage pq rows for b0 and b1, plus v (1024 floats each)
    {
        const float* __restrict__ pq0 = g_pq + (chunk * 8 + b0) * NA;
        const float* __restrict__ pq1 = g_pq + (chunk * 8 + b1) * NA;
        ((float4*)(smem + OFF_PQ))[t]        = ((const float4*)pq0)[t];
        ((float4*)(smem + OFF_PQ + 4096))[t] = ((const float4*)pq1)[t];
        ((float4*)(smem + OFF_V))[t]         = ((const float4*)v)[t];
    }

    // per-accumulator-row pq selection offsets
    uint32_t pqoff[8];
#pragma unroll
    for (int pi = 0; pi < 8; pi++) {
        const int row = WM + (pi >> 1) * 16 + (pi & 1) * 8 + (l >> 2);
        pqoff[pi] = (m0 + row >= bound) ? 4096u : 0u;
    }

    // loader mapping: 6 cp.async(16B) per stage per thread
    const int rA = t >> 2;                // 0..63
    const uint32_t q16 = (t & 3) * 16;
    const size_t chunkbase = (size_t)chunk * 8 * NS;
    const char* aBase = (const char*)(g_it16 + (chunkbase + m0 + rA) * NI) + q16;
    const char* bBase = (const char*)(g_ut16 + (size_t)rA * NI) + q16;
    const uint32_t dA = sb + STG_A + rA * PITCHB + q16;
    const uint32_t dB = sb + STG_B + rA * PITCHB + q16;
    const size_t R64  = (size_t)64 * NI * 2;    // 64 rows in bytes
    const size_t NT_B = (size_t)128 * NI * 2;   // one 128-n B panel in bytes

    // ldmatrix lane offsets (within stage)
    const uint32_t aOff = STG_A + (WM + (l & 15)) * PITCHB + (l >> 4) * 16;
    const uint32_t bOff = STG_B + (WN + (l & 7) + ((l >> 4) & 1) * 8) * PITCHB
                          + ((l >> 3) & 1) * 16;

    float acc[4][8][4];
    float p8[8];
#pragma unroll
    for (int i = 0; i < 8; i++) p8[i] = 0.f;

    // pipeline prologue: stages 0..2 (all nt=0)
#pragma unroll
    for (int p = 0; p < NSTG - 1; p++) {
        const uint32_t soff = p * STG_SZ;
        const size_t kb = (size_t)p * 64;
        const char* pa = aBase + kb;
        const char* pb = bBase + kb;
        CP16(dA + soff,                pa);
        CP16(dA + soff +  64 * PITCHB, pa + R64);
        CP16(dA + soff + 128 * PITCHB, pa + 2 * R64);
        CP16(dA + soff + 192 * PITCHB, pa + 3 * R64);
        CP16(dB + soff,                pb);
        CP16(dB + soff +  64 * PITCHB, pb + R64);
        CP_COMMIT();
    }

#pragma unroll 1
    for (int nt = 0; nt < NA / BNT; nt++) {
#pragma unroll
        for (int i = 0; i < 4; i++)
#pragma unroll
            for (int j = 0; j < 8; j++)
#pragma unroll
                for (int c = 0; c < 4; c++) acc[i][j][c] = 0.f;

#pragma unroll 4
        for (int ks = 0; ks < 32; ks++) {
            const int sg = nt * 32 + ks;
            const uint32_t sbase = (uint32_t)(sg & (NSTG - 1)) * STG_SZ;

            CP_WAIT2();
            __syncthreads();

            // issue stage sg+3
            const int s2 = sg + NSTG - 1;
            if (s2 < 256) {
                const int ks2 = s2 & 31, nt2 = s2 >> 5;
                const uint32_t soff = (uint32_t)(s2 & (NSTG - 1)) * STG_SZ;
                const size_t kb = (size_t)ks2 * 64;
                const char* pa = aBase + kb;
                const char* pb = bBase + (size_t)nt2 * NT_B + kb;
                CP16(dA + soff,                pa);
                CP16(dA + soff +  64 * PITCHB, pa + R64);
                CP16(dA + soff + 128 * PITCHB, pa + 2 * R64);
                CP16(dA + soff + 192 * PITCHB, pa + 3 * R64);
                CP16(dB + soff,                pb);
                CP16(dB + soff +  64 * PITCHB, pb + R64);
                CP_COMMIT();
            }

#pragma unroll
            for (int s = 0; s < 2; s++) {   // two k16 steps
                uint32_t Ah[4][4];
#pragma unroll
                for (int i = 0; i < 4; i++)
                    LDSM4(Ah[i], sb + sbase + aOff + i * 1280 + s * 32);
#pragma unroll
                for (int g = 0; g < 4; g++) {
                    uint32_t Bh[4];
                    LDSM4(Bh, sb + sbase + bOff + g * 1280 + s * 32);
#pragma unroll
                    for (int i = 0; i < 4; i++) {
                        MMAF16(acc[i][2 * g],     Ah[i], Bh[0], Bh[1]);
                        MMAF16(acc[i][2 * g + 1], Ah[i], Bh[2], Bh[3]);
                    }
                }
            }
        }

        // pass epilogue: MUFU tanh + dot(v), pq selected per row
#pragma unroll
        for (int j = 0; j < 8; j++) {
            const int n = nt * BNT + WN + j * 8 + (l & 3) * 2;
            const float2 v2 = *(const float2*)(smem + OFF_V + n * 4);
#pragma unroll
            for (int i = 0; i < 4; i++) {
#pragma unroll
                for (int h = 0; h < 2; h++) {
                    const int pi = i * 2 + h;
                    const float2 pq2 =
                        *(const float2*)(smem + OFF_PQ + pqoff[pi] + n * 4);
                    p8[pi] += tanha(acc[i][j][h * 2]     + pq2.x) * v2.x
                            + tanha(acc[i][j][h * 2 + 1] + pq2.y) * v2.y;
                }
            }
        }
    }

    // quad reduce (columns within quad), then cross-warpN reduce via smem
#pragma unroll
    for (int pi = 0; pi < 8; pi++) {
        float x = p8[pi];
        x += __shfl_xor_sync(0xffffffffu, x, 1);
        x += __shfl_xor_sync(0xffffffffu, x, 2);
        p8[pi] = x;
    }
    float* red = (float*)(smem + OFF_RED);
    if ((l & 3) == 0) {
#pragma unroll
        for (int pi = 0; pi < 8; pi++) {
            const int row = WM + (pi >> 1) * 16 + (pi & 1) * 8 + (l >> 2);
            red[(wid & 1) * 256 + row] = p8[pi];
        }
    }
    __syncthreads();
    if (m0 + t < chunkcnt) {
        const int bloc = (m0 + t >= bound) ? b1 : b0;
        const int j = m0 + t - loff[bloc];
        const int bg = chunk * 8 + bloc;
        const float sum = red[t] + red[256 + t];
        g_react[bg * NS + g_sidx[bg * NS + j]] = sum;
    }
}

// ---------------------------------------------------------------------------
// Kernel 3: masked softmax over S per batch; scores -> out.
// ---------------------------------------------------------------------------
__global__ void softmax_kernel(const int* __restrict__ weights,
                               float* __restrict__ out)
{
    const int b = blockIdx.x;
    const int t = threadIdx.x;
    __shared__ float sm[256];

    float vals[NS / 256];
    float mx = -INFINITY;
#pragma unroll
    for (int r = 0; r < NS / 256; r++) {
        const int s = t + r * 256;
        const float x = (weights[b * NS + s] == 0) ? -INFINITY
                                                   : g_react[b * NS + s];
        vals[r] = x;
        mx = fmaxf(mx, x);
    }
    sm[t] = mx; __syncthreads();
    for (int off = 128; off > 0; off >>= 1) {
        if (t < off) sm[t] = fmaxf(sm[t], sm[t + off]);
        __syncthreads();
    }
    mx = sm[0];
    __syncthreads();

    float sum = 0.f;
#pragma unroll
    for (int r = 0; r < NS / 256; r++) {
        vals[r] = expf(vals[r] - mx);
        sum += vals[r];
    }
    sm[t] = sum; __syncthreads();
    for (int off = 128; off > 0; off >>= 1) {
        if (t < off) sm[t] += sm[t + off];
        __syncthreads();
    }
    const float inv = 1.f / sm[0];

    float* scores = out + NB * NI + (size_t)b * NS;
#pragma unroll
    for (int r = 0; r < NS / 256; r++)
        scores[t + r * 256] = vals[r] * inv;
}

// ---------------------------------------------------------------------------
// Kernel 4a: blended partials (fp16 packed rows, LDG.128, 2 parity slots)
// ---------------------------------------------------------------------------
__global__ void blend_partial_kernel(const float* __restrict__ out)
{
    __shared__ float ws[NS / NCH];
    const int b   = blockIdx.x;
    const int ch  = blockIdx.y;
    const int j0  = ch * (NS / NCH);
    const int cnt = g_cnt[b];
    const float* __restrict__ scores = out + NB * NI + (size_t)b * NS;

    if (threadIdx.x < NS / NCH) {
        const int j = j0 + threadIdx.x;
        ws[threadIdx.x] = (j < cnt) ? scores[g_sidx[b * NS + j]] : 0.f;
    }
    __syncthreads();

    const int half = threadIdx.x >> 7;         // s parity
    const int col  = (threadIdx.x & 127) * 8;  // 8 halfs = 16B
    const __half* __restrict__ base =
        g_it16 + ((size_t)(g_woff[b] + j0)) * NI + col;

    float a0 = 0.f, a1 = 0.f, a2 = 0.f, a3 = 0.f;
    float a4 = 0.f, a5 = 0.f, a6 = 0.f, a7 = 0.f;
    for (int jj = half; jj < NS / NCH; jj += 2) {
        const float w = ws[jj];
        if (w != 0.f) {
            const uint4 hv = *(const uint4*)(base + (size_t)jj * NI);
            const float2 f0 = __half22float2(*reinterpret_cast<const __half2*>(&hv.x));
            const float2 f1 = __half22float2(*reinterpret_cast<const __half2*>(&hv.y));
            const float2 f2 = __half22float2(*reinterpret_cast<const __half2*>(&hv.z));
            const float2 f3 = __half22float2(*reinterpret_cast<const __half2*>(&hv.w));
            a0 = fmaf(w, f0.x, a0); a1 = fmaf(w, f0.y, a1);
            a2 = fmaf(w, f1.x, a2); a3 = fmaf(w, f1.y, a3);
            a4 = fmaf(w, f2.x, a4); a5 = fmaf(w, f2.y, a5);
            a6 = fmaf(w, f3.x, a6); a7 = fmaf(w, f3.y, a7);
        }
    }
    float* dst = g_bpart + (size_t)((b * NCH + ch) * 2 + half) * NI + col;
    *(float4*)(dst)     = make_float4(a0, a1, a2, a3);
    *(float4*)(dst + 4) = make_float4(a4, a5, a6, a7);
}

// ---------------------------------------------------------------------------
// Kernel 4b: reduce partials -> blended
// ---------------------------------------------------------------------------
__global__ void blend_reduce_kernel(float* __restrict__ out)
{
    const int b = blockIdx.x;
    const int i = threadIdx.x * 4;
    float4 acc = make_float4(0.f, 0.f, 0.f, 0.f);
    for (int c = 0; c < 2 * NCH; c++) {
        const float4 x = *(const float4*)(g_bpart + (size_t)(b * 2 * NCH + c) * NI + i);
        acc.x += x.x; acc.y += x.y; acc.z += x.z; acc.w += x.w;
    }
    *(float4*)(out + (size_t)b * NI + i) = acc;
}

// ---------------------------------------------------------------------------
extern "C" void kernel_launch(void* const* d_in, const int* in_sizes, int n_in,
                              void* d_out, int out_size)
{
    const float* queries = (const float*)d_in[0];
    const float* items   = (const float*)d_in[1];
    const int*   weights = (const int*)  d_in[2];
    const float* W       = (const float*)d_in[3];
    const float* U       = (const float*)d_in[4];
    const float* v       = (const float*)d_in[5];
    float* out = (float*)d_out;   // [B*I blended | B*S scores]

    // exactly R7's known-passing concurrency objects: 1 stream + 2 events
    static cudaStream_t s1 = nullptr;
    static cudaEvent_t eFork = nullptr, eJoin = nullptr;
    if (s1 == nullptr) {
        cudaFuncSetAttribute(react_kernel,
                             cudaFuncAttributeMaxDynamicSharedMemorySize, SM_TOTAL);
        cudaStreamCreateWithFlags(&s1, cudaStreamNonBlocking);
        cudaEventCreateWithFlags(&eFork, cudaEventDisableTiming);
        cudaEventCreateWithFlags(&eJoin, cudaEventDisableTiming);
    }

    // fork: pq + transpose on s1; compact -> prefix -> convert on main stream
    cudaEventRecord(eFork, 0);
    cudaStreamWaitEvent(s1, eFork, 0);
    pq_kernel<<<dim3(NB, NA / 256), 256, 0, s1>>>(queries, W);
    transpose_kernel<<<dim3(NA / 32, NI / 32), dim3(32, 8), 0, s1>>>(U);
    cudaEventRecord(eJoin, s1);

    compact_kernel<<<NB, 32>>>(weights);
    prefix_kernel<<<1, 32>>>();
    convert_items_kernel<<<dim3(NS / 4, NB), 256>>>(items);

    // join, then the dependent chain (react flattened: 64 tiles x 4 chunks)
    cudaStreamWaitEvent(0, eJoin, 0);
    react_kernel<<<dim3(8 * NS / BMT, NCHK), 256, SM_TOTAL>>>(v);
    softmax_kernel<<<NB, 256>>>(weights, out);
    blend_partial_kernel<<<dim3(NB, NCH), 256>>>(out);
    blend_reduce_kernel<<<NB, 256>>>(out);
}